// round 9
// baseline (speedup 1.0000x reference)
#include <cuda_runtime.h>
#include <cuda_bf16.h>
#include <math.h>
#include <stdint.h>

#define BB   128   // batch
#define SPP  128   // premise seq len
#define SHH  64    // hypothesis seq len
#define HH   1024  // hidden
#define EE   300   // embedding dim
#define EEP  320   // padded embedding K
#define G4   4096  // 4*H
#define VV   50000 // vocab

#define LUT_N    1024
#define LUT_D    (9.5f / 1023.0f)
#define LUT_INVD (1023.0f / 9.5f)

// ---------------- scratch (device globals; no runtime allocation) ----------------
__device__ float g_xwp[(size_t)SPP * BB * G4];
__device__ float g_xwh[(size_t)SHH * BB * G4];
__device__ float g_c[BB * HH];
__device__ float g_cc[BB * HH];
__device__ float g_outp[(size_t)BB * SPP * HH];  // Y, [b][p][h]
__device__ float g_outh[(size_t)SHH * BB * HH];  // [t][b][h]
__device__ float g_first[(size_t)BB * SPP * HH];
__device__ float g_second[BB * HH];
__device__ float g_trt[BB * HH];
__device__ float g_r[BB * HH];
__device__ float g_hstar[BB * HH];
__device__ float2 g_lut[LUT_N];                  // (tanh(i*D), centered slope/index)

// pre-split bf16 LSTM hidden state (ping/pong), written by LSTM epilogue
__device__ __nv_bfloat16 g_hsA_hi[BB * HH];
__device__ __nv_bfloat16 g_hsA_lo[BB * HH];
__device__ __nv_bfloat16 g_hsB_hi[BB * HH];
__device__ __nv_bfloat16 g_hsB_lo[BB * HH];

// pre-split bf16 weights (hi/lo)
__device__ __nv_bfloat16 c_emb_hi[(size_t)VV * EEP];
__device__ __nv_bfloat16 c_emb_lo[(size_t)VV * EEP];
__device__ __nv_bfloat16 c_wihp_hi[(size_t)G4 * EEP];
__device__ __nv_bfloat16 c_wihp_lo[(size_t)G4 * EEP];
__device__ __nv_bfloat16 c_wihh_hi[(size_t)G4 * EEP];
__device__ __nv_bfloat16 c_wihh_lo[(size_t)G4 * EEP];
__device__ __nv_bfloat16 c_whhp_hi[(size_t)G4 * HH];
__device__ __nv_bfloat16 c_whhp_lo[(size_t)G4 * HH];
__device__ __nv_bfloat16 c_whhh_hi[(size_t)G4 * HH];
__device__ __nv_bfloat16 c_whhh_lo[(size_t)G4 * HH];
__device__ __nv_bfloat16 c_wyt_hi[(size_t)HH * HH];   // wy^T: [n][k]
__device__ __nv_bfloat16 c_wyt_lo[(size_t)HH * HH];

// ---------------- helpers ----------------
__device__ __forceinline__ float sigm(float x) { return 1.f / (1.f + expf(-x)); }

// LUT tanh: |err| ~8e-6, no MUFU, no F2I (magic-add index extraction)
__device__ __forceinline__ float tanh_lut(float x, const float2* lut) {
    float t = fminf(fabsf(x) * LUT_INVD, 1023.0f);
    float m = t + 12582912.0f;                 // 1.5*2^23: RN -> round(t) in mantissa
    int   i = __float_as_int(m) & 0x3FF;
    float fr = t - (m - 12582912.0f);          // [-0.5, 0.5] in index units
    float2 e = lut[i];
    float v = fmaf(fr, e.y, e.x);              // v >= 0 always
    return __int_as_float((__float_as_int(x) & 0x80000000) | __float_as_int(v));
}

__global__ void k_build_lut() {
    int i = threadIdx.x;
    float v  = tanhf(i * LUT_D);
    float vp = tanhf((i + 1) * LUT_D);
    float vm = tanhf((i - 1) * LUT_D);
    g_lut[i] = make_float2(v, (vp - vm) * 0.5f);
}

__device__ __forceinline__ void mma16816(float4& d, const uint32_t* a, const uint32_t* b) {
    asm volatile(
        "mma.sync.aligned.m16n8k16.row.col.f32.bf16.bf16.f32 "
        "{%0,%1,%2,%3},{%4,%5,%6,%7},{%8,%9},{%0,%1,%2,%3};\n"
        : "+f"(d.x), "+f"(d.y), "+f"(d.z), "+f"(d.w)
        : "r"(a[0]), "r"(a[1]), "r"(a[2]), "r"(a[3]), "r"(b[0]), "r"(b[1]));
}

// convert 8 consecutive fp32 -> packed bf16 hi/lo (4 u32 each)
__device__ __forceinline__ void split_pack8(const float* g, uint32_t* ah, uint32_t* al) {
    float4 v0 = *(const float4*)g, v1 = *(const float4*)(g + 4);
    float f[8] = {v0.x, v0.y, v0.z, v0.w, v1.x, v1.y, v1.z, v1.w};
    #pragma unroll
    for (int i = 0; i < 4; i++) {
        __nv_bfloat16 h0 = __float2bfloat16(f[2*i]);
        __nv_bfloat16 h1 = __float2bfloat16(f[2*i+1]);
        __nv_bfloat162 hh; hh.x = h0; hh.y = h1;
        ah[i] = *(uint32_t*)&hh;
        __nv_bfloat162 ll;
        ll.x = __float2bfloat16(f[2*i]   - __bfloat162float(h0));
        ll.y = __float2bfloat16(f[2*i+1] - __bfloat162float(h1));
        al[i] = *(uint32_t*)&ll;
    }
}

// fragment compute over one 32-k chunk (smem tiles bf16 [64][40])
__device__ __forceinline__ void mma_chunk(
    const __nv_bfloat16* sAh, const __nv_bfloat16* sAl,
    const __nv_bfloat16* sBh, const __nv_bfloat16* sBl,
    int warp_m, int warp_n, int lane, float4 c[2][2])
{
    int grp = lane >> 2, tig = lane & 3;
    #pragma unroll
    for (int ks = 0; ks < 32; ks += 16) {
        uint32_t ah[2][4], al[2][4], bh[2][2], bl[2][2];
        #pragma unroll
        for (int i = 0; i < 2; i++) {
            int r = warp_m * 32 + i * 16 + grp;
            const __nv_bfloat16* ph = sAh + r * 40 + ks + tig * 2;
            const __nv_bfloat16* pl = sAl + r * 40 + ks + tig * 2;
            ah[i][0] = *(const uint32_t*)(ph);
            ah[i][1] = *(const uint32_t*)(ph + 8 * 40);
            ah[i][2] = *(const uint32_t*)(ph + 8);
            ah[i][3] = *(const uint32_t*)(ph + 8 * 40 + 8);
            al[i][0] = *(const uint32_t*)(pl);
            al[i][1] = *(const uint32_t*)(pl + 8 * 40);
            al[i][2] = *(const uint32_t*)(pl + 8);
            al[i][3] = *(const uint32_t*)(pl + 8 * 40 + 8);
        }
        #pragma unroll
        for (int j = 0; j < 2; j++) {
            int n = warp_n * 16 + j * 8 + grp;
            const __nv_bfloat16* ph = sBh + n * 40 + ks + tig * 2;
            const __nv_bfloat16* pl = sBl + n * 40 + ks + tig * 2;
            bh[j][0] = *(const uint32_t*)(ph);
            bh[j][1] = *(const uint32_t*)(ph + 8);
            bl[j][0] = *(const uint32_t*)(pl);
            bl[j][1] = *(const uint32_t*)(pl + 8);
        }
        #pragma unroll
        for (int i = 0; i < 2; i++)
            #pragma unroll
            for (int j = 0; j < 2; j++) {
                mma16816(c[i][j], ah[i], bh[j]);
                mma16816(c[i][j], ah[i], bl[j]);
                mma16816(c[i][j], al[i], bh[j]);
            }
    }
}

// ---------------- weight prep: fp32 -> bf16 hi/lo (with K padding) ----------------
__global__ void k_cvt(const float* __restrict__ src, __nv_bfloat16* __restrict__ hi,
                      __nv_bfloat16* __restrict__ lo, int C, int Cp, long total)
{
    long idx = (long)blockIdx.x * blockDim.x + threadIdx.x;
    if (idx >= total) return;
    long r = idx / Cp; int cc = (int)(idx % Cp);
    float v = (cc < C) ? src[r * C + cc] : 0.f;
    __nv_bfloat16 h = __float2bfloat16(v);
    hi[idx] = h;
    lo[idx] = __float2bfloat16(v - __bfloat162float(h));
}
__global__ void k_cvt_t(const float* __restrict__ src)  // wy [K][N] -> [n][k]
{
    int idx = blockIdx.x * blockDim.x + threadIdx.x;   // n*HH + k
    int n = idx >> 10, k = idx & 1023;
    float v = src[(size_t)k * HH + n];
    __nv_bfloat16 h = __float2bfloat16(v);
    c_wyt_hi[idx] = h;
    c_wyt_lo[idx] = __float2bfloat16(v - __bfloat162float(h));
}

// ---------------- init / prep ----------------
__global__ void k_init() {
    int i = blockIdx.x * blockDim.x + threadIdx.x;
    if (i < BB * HH) {
        g_c[i] = 0.f; g_cc[i] = 0.f; g_r[i] = 0.f;
        __nv_bfloat16 z = __float2bfloat16(0.f);
        g_hsA_hi[i] = z; g_hsA_lo[i] = z;
        g_hsB_hi[i] = z; g_hsB_lo[i] = z;
    }
}
__global__ void k_prep_hyp() {   // h0 = 0 (parity-0 split buffers), c0 = masked last premise cell
    int i = blockIdx.x * blockDim.x + threadIdx.x;
    if (i < BB * HH) {
        g_c[i] = g_cc[i];
        __nv_bfloat16 z = __float2bfloat16(0.f);
        g_hsA_hi[i] = z; g_hsA_lo[i] = z;
    }
}

// ---------------- mma embed: out = gather(emb)[M x K] @ wih^T + biases ----------------
__global__ void __launch_bounds__(256) k_mma_embed(
    const int* __restrict__ toks, int S,
    const __nv_bfloat16* __restrict__ Bhi, const __nv_bfloat16* __restrict__ Blo,
    const float* __restrict__ bih, const float* __restrict__ bhh, float* __restrict__ outp)
{
    __shared__ __nv_bfloat16 sAh[64*40], sAl[64*40], sBh[64*40], sBl[64*40];
    __shared__ int stok[64];
    int tid = threadIdx.x, lane = tid & 31, wid = tid >> 5;
    int warp_m = wid >> 2, warp_n = wid & 3;
    int m0 = blockIdx.y * 64, n0 = blockIdx.x * 64;
    if (tid < 64) { int m = m0 + tid; stok[tid] = toks[(m & (BB-1)) * S + (m >> 7)]; }
    __syncthreads();

    int srow = tid >> 2, skq = (tid & 3) * 8;
    const __nv_bfloat16* arow_hi;
    const __nv_bfloat16* arow_lo;
    {
        size_t base = (size_t)stok[srow] * EEP;
        arow_hi = c_emb_hi + base; arow_lo = c_emb_lo + base;
    }
    size_t bbase = (size_t)(n0 + srow) * EEP;

    float4 c[2][2] = {};
    uint4 pAh, pAl, pBh, pBl;
    pAh = *(const uint4*)(arow_hi + skq);
    pAl = *(const uint4*)(arow_lo + skq);
    pBh = *(const uint4*)(Bhi + bbase + skq);
    pBl = *(const uint4*)(Blo + bbase + skq);

    const int KC = EEP / 32;
    for (int ck = 0; ck < KC; ck++) {
        *(uint4*)&sAh[srow*40 + skq] = pAh;
        *(uint4*)&sAl[srow*40 + skq] = pAl;
        *(uint4*)&sBh[srow*40 + skq] = pBh;
        *(uint4*)&sBl[srow*40 + skq] = pBl;
        __syncthreads();
        if (ck + 1 < KC) {
            int k0 = (ck + 1) * 32;
            pAh = *(const uint4*)(arow_hi + k0 + skq);
            pAl = *(const uint4*)(arow_lo + k0 + skq);
            pBh = *(const uint4*)(Bhi + bbase + k0 + skq);
            pBl = *(const uint4*)(Blo + bbase + k0 + skq);
        }
        mma_chunk(sAh, sAl, sBh, sBl, warp_m, warp_n, lane, c);
        __syncthreads();
    }

    int grp = lane >> 2, tig = lane & 3;
    #pragma unroll
    for (int i = 0; i < 2; i++) {
        int r = m0 + warp_m * 32 + i * 16 + grp;
        #pragma unroll
        for (int j = 0; j < 2; j++) {
            int n = n0 + warp_n * 16 + j * 8 + tig * 2;
            float b0 = bih[n] + bhh[n], b1 = bih[n+1] + bhh[n+1];
            outp[(size_t)r * G4 + n]       = c[i][j].x + b0;
            outp[(size_t)r * G4 + n + 1]   = c[i][j].y + b1;
            outp[(size_t)(r+8) * G4 + n]   = c[i][j].z + b0;
            outp[(size_t)(r+8) * G4 + n+1] = c[i][j].w + b1;
        }
    }
}

// ---------------- mma first: g_first = g_outp @ wy  (A fp32 on-the-fly split) ----------------
__global__ void __launch_bounds__(256) k_mma_first()
{
    __shared__ __nv_bfloat16 sAh[64*40], sAl[64*40], sBh[64*40], sBl[64*40];
    int tid = threadIdx.x, lane = tid & 31, wid = tid >> 5;
    int warp_m = wid >> 2, warp_n = wid & 3;
    int m0 = blockIdx.y * 64, n0 = blockIdx.x * 64;

    int srow = tid >> 2, skq = (tid & 3) * 8;
    const float* arow = g_outp + (size_t)(m0 + srow) * HH;
    size_t bbase = (size_t)(n0 + srow) * HH;

    float4 c[2][2] = {};
    uint32_t pAh[4], pAl[4]; uint4 pBh, pBl;
    split_pack8(arow + skq, pAh, pAl);
    pBh = *(const uint4*)(c_wyt_hi + bbase + skq);
    pBl = *(const uint4*)(c_wyt_lo + bbase + skq);

    const int KC = HH / 32;
    for (int ck = 0; ck < KC; ck++) {
        *(uint4*)&sAh[srow*40 + skq] = make_uint4(pAh[0], pAh[1], pAh[2], pAh[3]);
        *(uint4*)&sAl[srow*40 + skq] = make_uint4(pAl[0], pAl[1], pAl[2], pAl[3]);
        *(uint4*)&sBh[srow*40 + skq] = pBh;
        *(uint4*)&sBl[srow*40 + skq] = pBl;
        __syncthreads();
        if (ck + 1 < KC) {
            int k0 = (ck + 1) * 32;
            split_pack8(arow + k0 + skq, pAh, pAl);
            pBh = *(const uint4*)(c_wyt_hi + bbase + k0 + skq);
            pBl = *(const uint4*)(c_wyt_lo + bbase + k0 + skq);
        }
        mma_chunk(sAh, sAl, sBh, sBl, warp_m, warp_n, lane, c);
        __syncthreads();
    }

    int grp = lane >> 2, tig = lane & 3;
    #pragma unroll
    for (int i = 0; i < 2; i++) {
        int r = m0 + warp_m * 32 + i * 16 + grp;
        #pragma unroll
        for (int j = 0; j < 2; j++) {
            int n = n0 + warp_n * 16 + j * 8 + tig * 2;
            g_first[(size_t)r * HH + n]       = c[i][j].x;
            g_first[(size_t)r * HH + n + 1]   = c[i][j].y;
            g_first[(size_t)(r+8) * HH + n]   = c[i][j].z;
            g_first[(size_t)(r+8) * HH + n+1] = c[i][j].w;
        }
    }
}

// ---------------- mma LSTM step (fused pointwise, pre-split h state) ----------------
// Block: 64 batch x (16 h-cols x 4 gates). Grid: dim3(HH/16=64, 2).
__global__ void __launch_bounds__(256) k_mma_lstm(
    const __nv_bfloat16* __restrict__ Whi, const __nv_bfloat16* __restrict__ Wlo,
    const float* __restrict__ xw, const int* __restrict__ toks, int S, int t, int which)
{
    const __nv_bfloat16* hin_hi = (t & 1) ? g_hsB_hi : g_hsA_hi;
    const __nv_bfloat16* hin_lo = (t & 1) ? g_hsB_lo : g_hsA_lo;
    __nv_bfloat16* hout_hi = (t & 1) ? g_hsA_hi : g_hsB_hi;
    __nv_bfloat16* hout_lo = (t & 1) ? g_hsA_lo : g_hsB_lo;

    __shared__ __align__(16) char pool[64*40*2*4 + 64*68*4];
    __nv_bfloat16* sAh = (__nv_bfloat16*)pool;
    __nv_bfloat16* sAl = sAh + 64*40;
    __nv_bfloat16* sBh = sAl + 64*40;
    __nv_bfloat16* sBl = sBh + 64*40;
    float* Gs = (float*)(pool + 64*40*2*4);   // [64][68]

    int tid = threadIdx.x, lane = tid & 31, wid = tid >> 5;
    int warp_m = wid >> 2, warp_n = wid & 3;
    int m0 = blockIdx.y * 64;        // batch offset
    int h0 = blockIdx.x * 16;        // h-col offset

    int srow = tid >> 2, skq = (tid & 3) * 8;
    const __nv_bfloat16* arow_hi = hin_hi + (size_t)(m0 + srow) * HH;
    const __nv_bfloat16* arow_lo = hin_lo + (size_t)(m0 + srow) * HH;
    int gate = srow >> 4, hh = srow & 15;
    size_t bbase = (size_t)(gate * HH + h0 + hh) * HH;

    float4 c[2][2] = {};
    uint4 pAh, pAl, pBh, pBl;
    pAh = *(const uint4*)(arow_hi + skq);
    pAl = *(const uint4*)(arow_lo + skq);
    pBh = *(const uint4*)(Whi + bbase + skq);
    pBl = *(const uint4*)(Wlo + bbase + skq);

    const int KC = HH / 32;
    for (int ck = 0; ck < KC; ck++) {
        *(uint4*)&sAh[srow*40 + skq] = pAh;
        *(uint4*)&sAl[srow*40 + skq] = pAl;
        *(uint4*)&sBh[srow*40 + skq] = pBh;
        *(uint4*)&sBl[srow*40 + skq] = pBl;
        __syncthreads();
        if (ck + 1 < KC) {
            int k0 = (ck + 1) * 32;
            pAh = *(const uint4*)(arow_hi + k0 + skq);
            pAl = *(const uint4*)(arow_lo + k0 + skq);
            pBh = *(const uint4*)(Whi + bbase + k0 + skq);
            pBl = *(const uint4*)(Wlo + bbase + k0 + skq);
        }
        mma_chunk(sAh, sAl, sBh, sBl, warp_m, warp_n, lane, c);
        __syncthreads();
    }

    // gate preactivations -> Gs[batch64][col = gate*16 + hh]
    {
        int grp = lane >> 2, tig = lane & 3;
        #pragma unroll
        for (int i = 0; i < 2; i++) {
            int r = warp_m * 32 + i * 16 + grp;
            #pragma unroll
            for (int j = 0; j < 2; j++) {
                int n = warp_n * 16 + j * 8 + tig * 2;
                Gs[r * 68 + n]         = c[i][j].x;
                Gs[r * 68 + n + 1]     = c[i][j].y;
                Gs[(r+8) * 68 + n]     = c[i][j].z;
                Gs[(r+8) * 68 + n + 1] = c[i][j].w;
            }
        }
    }
    __syncthreads();

    // pointwise: thread handles 4 consecutive h of one batch row
    {
        int q = tid * 4;
        int b64 = q >> 4, hh4 = q & 15;
        int b = m0 + b64;
        int h = h0 + hh4;
        float m = (toks[b * S + t] != 0) ? 1.f : 0.f;
        float im = 1.f - m;
        const float* xr = xw + ((size_t)t * BB + b) * G4 + h;
        float4 gi = *(float4*)&Gs[b64 * 68 +  0 + hh4];
        float4 gf = *(float4*)&Gs[b64 * 68 + 16 + hh4];
        float4 gg = *(float4*)&Gs[b64 * 68 + 32 + hh4];
        float4 go = *(float4*)&Gs[b64 * 68 + 48 + hh4];
        float4 xi = *(const float4*)&xr[0 * HH];
        float4 xf = *(const float4*)&xr[1 * HH];
        float4 xg = *(const float4*)&xr[2 * HH];
        float4 xo = *(const float4*)&xr[3 * HH];
        float4 cc = *(float4*)&g_c[b * HH + h];
        float giv[4] = {gi.x + xi.x, gi.y + xi.y, gi.z + xi.z, gi.w + xi.w};
        float gfv[4] = {gf.x + xf.x, gf.y + xf.y, gf.z + xf.z, gf.w + xf.w};
        float ggv[4] = {gg.x + xg.x, gg.y + xg.y, gg.z + xg.z, gg.w + xg.w};
        float gov[4] = {go.x + xo.x, go.y + xo.y, go.z + xo.z, go.w + xo.w};
        float cv[4] = {cc.x, cc.y, cc.z, cc.w};
        float c2v[4], h2v[4];
        #pragma unroll
        for (int i = 0; i < 4; i++) {
            float iv = sigm(giv[i]), fv = sigm(gfv[i]);
            float gv = tanhf(ggv[i]), ov = sigm(gov[i]);
            float c2 = fv * cv[i] + iv * gv;
            c2v[i] = c2;
            h2v[i] = ov * tanhf(c2);
        }
        float4 c2f = make_float4(c2v[0], c2v[1], c2v[2], c2v[3]);
        float4 h2f = make_float4(h2v[0], h2v[1], h2v[2], h2v[3]);
        *(float4*)&g_c[b * HH + h] = c2f;

        // write raw h as bf16 hi/lo split (next step's A operand)
        {
            __nv_bfloat162 hi01, hi23, lo01, lo23;
            hi01.x = __float2bfloat16(h2v[0]); hi01.y = __float2bfloat16(h2v[1]);
            hi23.x = __float2bfloat16(h2v[2]); hi23.y = __float2bfloat16(h2v[3]);
            lo01.x = __float2bfloat16(h2v[0] - __bfloat162float(hi01.x));
            lo01.y = __float2bfloat16(h2v[1] - __bfloat162float(hi01.y));
            lo23.x = __float2bfloat16(h2v[2] - __bfloat162float(hi23.x));
            lo23.y = __float2bfloat16(h2v[3] - __bfloat162float(hi23.y));
            uint2 phi = make_uint2(*(uint32_t*)&hi01, *(uint32_t*)&hi23);
            uint2 plo = make_uint2(*(uint32_t*)&lo01, *(uint32_t*)&lo23);
            *(uint2*)&hout_hi[b * HH + h] = phi;
            *(uint2*)&hout_lo[b * HH + h] = plo;
        }

        if (which == 0) {
            float4 prev = make_float4(0.f, 0.f, 0.f, 0.f);
            if (t > 0) prev = *(float4*)&g_outp[((size_t)b * SPP + (t - 1)) * HH + h];
            *(float4*)&g_outp[((size_t)b * SPP + t) * HH + h] = make_float4(
                m * h2f.x + im * prev.x, m * h2f.y + im * prev.y,
                m * h2f.z + im * prev.z, m * h2f.w + im * prev.w);
            float4 pc = *(float4*)&g_cc[b * HH + h];
            *(float4*)&g_cc[b * HH + h] = make_float4(
                m * c2f.x + im * pc.x, m * c2f.y + im * pc.y,
                m * c2f.z + im * pc.z, m * c2f.w + im * pc.w);
        } else {
            float4 prev = make_float4(0.f, 0.f, 0.f, 0.f);
            if (t > 0) prev = *(float4*)&g_outh[((size_t)(t - 1) * BB + b) * HH + h];
            *(float4*)&g_outh[((size_t)t * BB + b) * HH + h] = make_float4(
                m * h2f.x + im * prev.x, m * h2f.y + im * prev.y,
                m * h2f.z + im * prev.z, m * h2f.w + im * prev.w);
        }
    }
}

// ---------------- fused second + trt (fp32 SIMT, proven numerics) ----------------
__global__ void __launch_bounds__(256) k_secondtrt(
    const float* __restrict__ wh_, const float* __restrict__ wr_,
    const float* __restrict__ wt_, int t)
{
    __shared__ float As1[32][68];   // outh_t
    __shared__ float As2[32][68];   // r
    __shared__ float Bs1[32][36];
    __shared__ float Bs2[32][36];
    __shared__ float Bs3[32][36];
    const float* A1 = g_outh + (size_t)t * BB * HH;
    const int K = HH, N = HH;
    int tid = threadIdx.x;
    int n0 = blockIdx.x * 32, m0 = blockIdx.y * 64;
    int ty = tid / 8, tx = tid % 8;
    int alm = tid / 4, alk = (tid % 4) * 8;
    float acc1[2][4] = {};
    float acc2[2][4] = {};

    for (int k0 = 0; k0 < K; k0 += 32) {
        {
            const float4* ap = (const float4*)&A1[(size_t)(m0 + alm) * K + k0 + alk];
            float4 v0 = ap[0], v1 = ap[1];
            As1[alk + 0][alm] = v0.x; As1[alk + 1][alm] = v0.y; As1[alk + 2][alm] = v0.z; As1[alk + 3][alm] = v0.w;
            As1[alk + 4][alm] = v1.x; As1[alk + 5][alm] = v1.y; As1[alk + 6][alm] = v1.z; As1[alk + 7][alm] = v1.w;
        }
        {
            const float4* ap = (const float4*)&g_r[(size_t)(m0 + alm) * K + k0 + alk];
            float4 v0 = ap[0], v1 = ap[1];
            As2[alk + 0][alm] = v0.x; As2[alk + 1][alm] = v0.y; As2[alk + 2][alm] = v0.z; As2[alk + 3][alm] = v0.w;
            As2[alk + 4][alm] = v1.x; As2[alk + 5][alm] = v1.y; As2[alk + 6][alm] = v1.z; As2[alk + 7][alm] = v1.w;
        }
        {
            int bk = tid / 8, bn = (tid % 8) * 4;
            *(float4*)&Bs1[bk][bn] = *(const float4*)&wh_[(size_t)(k0 + bk) * N + n0 + bn];
            *(float4*)&Bs2[bk][bn] = *(const float4*)&wr_[(size_t)(k0 + bk) * N + n0 + bn];
            *(float4*)&Bs3[bk][bn] = *(const float4*)&wt_[(size_t)(k0 + bk) * N + n0 + bn];
        }
        __syncthreads();
        #pragma unroll
        for (int k = 0; k < 32; k++) {
            float a0 = As1[k][ty * 2 + 0], a1 = As1[k][ty * 2 + 1];
            float c0 = As2[k][ty * 2 + 0], c1 = As2[k][ty * 2 + 1];
            float4 b1 = *(const float4*)&Bs1[k][tx * 4];
            float4 b2 = *(const float4*)&Bs2[k][tx * 4];
            float4 b3 = *(const float4*)&Bs3[k][tx * 4];
            acc1[0][0] += a0 * b1.x + c0 * b2.x; acc1[0][1] += a0 * b1.y + c0 * b2.y;
            acc1[0][2] += a0 * b1.z + c0 * b2.z; acc1[0][3] += a0 * b1.w + c0 * b2.w;
            acc1[1][0] += a1 * b1.x + c1 * b2.x; acc1[1][1] += a1 * b1.y + c1 * b2.y;
            acc1[1][2] += a1 * b1.z + c1 * b2.z; acc1[1][3] += a1 * b1.w + c1 * b2.w;
            acc2[0][0] += c0 * b3.x; acc2[0][1] += c0 * b3.y; acc2[0][2] += c0 * b3.z; acc2[0][3] += c0 * b3.w;
            acc2[1][0] += c1 * b3.x; acc2[1][1] += c1 * b3.y; acc2[1][2] += c1 * b3.z; acc2[1][3] += c1 * b3.w;
        }
        __syncthreads();
    }
    #pragma unroll
    for (int i = 0; i < 2; i++) {
        int m = m0 + ty * 2 + i;
        #pragma unroll
        for (int j = 0; j < 4; j++) {
            int n = n0 + tx * 4 + j;
            g_second[(size_t)m * HH + n] = acc1[i][j];
            g_trt[(size_t)m * HH + n]    = acc2[i][j];
        }
    }
}

// ---------------- fused scan step: score (LUT) + softmax + r update, one block per b ----------------
__global__ void __launch_bounds__(512) k_scanstep(const int* __restrict__ prem,
                                                  const int* __restrict__ hyp,
                                                  const float* __restrict__ w_, int t)
{
    __shared__ float2 slut[LUT_N];
    __shared__ float ssec[HH];
    __shared__ float sw[HH];
    __shared__ float sc[SPP];
    __shared__ float al[SPP];
    int b = blockIdx.x, tid = threadIdx.x;
    int lane = tid & 31, wid = tid >> 5;

    slut[tid]       = g_lut[tid];
    slut[tid + 512] = g_lut[tid + 512];
    ssec[tid]       = g_second[b * HH + tid];
    ssec[tid + 512] = g_second[b * HH + tid + 512];
    sw[tid]         = w_[tid];
    sw[tid + 512]   = w_[tid + 512];
    __syncthreads();

    // scores: warp w handles p = w*8 .. w*8+7
    #pragma unroll 1
    for (int i = 0; i < 8; i++) {
        int p = wid * 8 + i;
        const float4* frow = (const float4*)(g_first + ((size_t)b * SPP + p) * HH);
        float acc = 0.f;
        #pragma unroll
        for (int j = 0; j < 8; j++) {
            int idx = j * 32 + lane;
            float4 f  = frow[idx];
            float4 s  = *(const float4*)&ssec[idx * 4];
            float4 ww = *(const float4*)&sw[idx * 4];
            acc += tanh_lut(f.x + s.x, slut) * ww.x + tanh_lut(f.y + s.y, slut) * ww.y
                 + tanh_lut(f.z + s.z, slut) * ww.z + tanh_lut(f.w + s.w, slut) * ww.w;
        }
        #pragma unroll
        for (int o = 16; o > 0; o >>= 1) acc += __shfl_down_sync(0xffffffffu, acc, o);
        if (lane == 0)
            sc[p] = acc + ((prem[b * SPP + p] != 0) ? 0.f : -1000.f);
    }
    __syncthreads();

    // softmax by warp 0
    if (wid == 0) {
        float v0 = sc[lane], v1 = sc[lane+32], v2 = sc[lane+64], v3 = sc[lane+96];
        float mx = fmaxf(fmaxf(v0, v1), fmaxf(v2, v3));
        #pragma unroll
        for (int o = 16; o > 0; o >>= 1) mx = fmaxf(mx, __shfl_xor_sync(0xffffffffu, mx, o));
        float e0 = expf(v0-mx), e1 = expf(v1-mx), e2 = expf(v2-mx), e3 = expf(v3-mx);
        float ss = e0 + e1 + e2 + e3;
        #pragma unroll
        for (int o = 16; o > 0; o >>= 1) ss += __shfl_xor_sync(0xffffffffu, ss, o);
        float inv = 1.f / ss;
        al[lane]    = e0 * inv; al[lane+32] = e1 * inv;
        al[lane+64] = e2 * inv; al[lane+96] = e3 * inv;
    }
    __syncthreads();

    // r update: r_t[h] = sum_p al[p]*Y[b][p][h] + tanh(trt); mask-carry
    {
        int h = tid * 2;
        const float* yb = g_outp + (size_t)b * SPP * HH + h;
        float ax = 0.f, ay = 0.f;
        #pragma unroll 4
        for (int p = 0; p < SPP; p++) {
            float a = al[p];
            float2 y = *(const float2*)&yb[(size_t)p * HH];
            ax += a * y.x; ay += a * y.y;
        }
        float2 tr = *(const float2*)&g_trt[b * HH + h];
        float rt0 = ax + tanhf(tr.x);
        float rt1 = ay + tanhf(tr.y);
        float m = (hyp[b * SHH + t] != 0) ? 1.f : 0.f;
        float im = 1.f - m;
        float2 r = *(float2*)&g_r[b * HH + h];
        *(float2*)&g_r[b * HH + h] = make_float2(m * rt0 + im * r.x, m * rt1 + im * r.y);
    }
}

// ---------------- small-M fp32 GEMM (h_star) ----------------
__global__ void __launch_bounds__(256) k_hstar(const float* __restrict__ wp_, const float* __restrict__ wx_)
{
    __shared__ float As1[32][68];
    __shared__ float As2[32][68];
    __shared__ float Bs1[32][36];
    __shared__ float Bs2[32][36];
    const float* A1 = g_r;
    const float* A2 = g_outh + (size_t)(SHH - 1) * BB * HH;
    const int K = HH, N = HH;
    int tid = threadIdx.x;
    int n0 = blockIdx.x * 32, m0 = blockIdx.y * 64;
    int ty = tid / 8, tx = tid % 8;
    int alm = tid / 4, alk = (tid % 4) * 8;
    float acc[2][4] = {};

    for (int k0 = 0; k0 < K; k0 += 32) {
        {
            const float4* ap = (const float4*)&A1[(size_t)(m0 + alm) * K + k0 + alk];
            float4 v0 = ap[0], v1 = ap[1];
            As1[alk + 0][alm] = v0.x; As1[alk + 1][alm] = v0.y; As1[alk + 2][alm] = v0.z; As1[alk + 3][alm] = v0.w;
            As1[alk + 4][alm] = v1.x; As1[alk + 5][alm] = v1.y; As1[alk + 6][alm] = v1.z; As1[alk + 7][alm] = v1.w;
        }
        {
            const float4* ap = (const float4*)&A2[(size_t)(m0 + alm) * K + k0 + alk];
            float4 v0 = ap[0], v1 = ap[1];
            As2[alk + 0][alm] = v0.x; As2[alk + 1][alm] = v0.y; As2[alk + 2][alm] = v0.z; As2[alk + 3][alm] = v0.w;
            As2[alk + 4][alm] = v1.x; As2[alk + 5][alm] = v1.y; As2[alk + 6][alm] = v1.z; As2[alk + 7][alm] = v1.w;
        }
        {
            int bk = tid / 8, bn = (tid % 8) * 4;
            *(float4*)&Bs1[bk][bn] = *(const float4*)&wp_[(size_t)(k0 + bk) * N + n0 + bn];
            *(float4*)&Bs2[bk][bn] = *(const float4*)&wx_[(size_t)(k0 + bk) * N + n0 + bn];
        }
        __syncthreads();
        #pragma unroll
        for (int k = 0; k < 32; k++) {
            float a0 = As1[k][ty * 2 + 0], a1 = As1[k][ty * 2 + 1];
            float c0 = As2[k][ty * 2 + 0], c1 = As2[k][ty * 2 + 1];
            float4 b = *(const float4*)&Bs1[k][tx * 4];
            float4 d = *(const float4*)&Bs2[k][tx * 4];
            acc[0][0] += a0 * b.x + c0 * d.x; acc[0][1] += a0 * b.y + c0 * d.y;
            acc[0][2] += a0 * b.z + c0 * d.z; acc[0][3] += a0 * b.w + c0 * d.w;
            acc[1][0] += a1 * b.x + c1 * d.x; acc[1][1] += a1 * b.y + c1 * d.y;
            acc[1][2] += a1 * b.z + c1 * d.z; acc[1][3] += a1 * b.w + c1 * d.w;
        }
        __syncthreads();
    }
    #pragma unroll
    for (int i = 0; i < 2; i++) {
        int m = m0 + ty * 2 + i;
        #pragma unroll
        for (int j = 0; j < 4; j++)
            g_hstar[(size_t)m * N + n0 + tx * 4 + j] = acc[i][j];
    }
}

// ---------------- logits + final softmax ----------------
__global__ void __launch_bounds__(256) k_logits(const float* __restrict__ fcw,
                                                const float* __restrict__ fcb,
                                                float* __restrict__ out)
{
    int b = blockIdx.x, tid = threadIdx.x;
    float a0 = 0.f, a1 = 0.f, a2 = 0.f, a3 = 0.f;
    for (int h = tid; h < HH; h += 256) {
        float hs = tanhf(g_hstar[b * HH + h]);
        a0 += hs * fcw[0 * HH + h];
        a1 += hs * fcw[1 * HH + h];
        a2 += hs * fcw[2 * HH + h];
        a3 += hs * fcw[3 * HH + h];
    }
    __shared__ float sm[4][256];
    sm[0][tid] = a0; sm[1][tid] = a1; sm[2][tid] = a2; sm[3][tid] = a3;
    __syncthreads();
    for (int s = 128; s > 0; s >>= 1) {
        if (tid < s) {
            #pragma unroll
            for (int c = 0; c < 4; c++) sm[c][tid] += sm[c][tid + s];
        }
        __syncthreads();
    }
    if (tid == 0) {
        float l[4]; float mx = -1e30f;
        #pragma unroll
        for (int c = 0; c < 4; c++) { l[c] = sm[c][0] + fcb[c]; mx = fmaxf(mx, l[c]); }
        float s = 0.f;
        #pragma unroll
        for (int c = 0; c < 4; c++) { l[c] = expf(l[c] - mx); s += l[c]; }
        #pragma unroll
        for (int c = 0; c < 4; c++) out[b * 4 + c] = l[c] / s;
    }
}

// ---------------- launch ----------------
extern "C" void kernel_launch(void* const* d_in, const int* in_sizes, int n_in,
                              void* d_out, int out_size)
{
    (void)in_sizes; (void)n_in; (void)out_size;
    const int*   prem   = (const int*)d_in[0];
    const int*   hyp    = (const int*)d_in[1];
    const float* emb    = (const float*)d_in[2];
    const float* w_ih_p = (const float*)d_in[3];
    const float* w_hh_p = (const float*)d_in[4];
    const float* b_ih_p = (const float*)d_in[5];
    const float* b_hh_p = (const float*)d_in[6];
    const float* w_ih_h = (const float*)d_in[7];
    const float* w_hh_h = (const float*)d_in[8];
    const float* b_ih_h = (const float*)d_in[9];
    const float* b_hh_h = (const float*)d_in[10];
    const float* wy     = (const float*)d_in[11];
    const float* wh     = (const float*)d_in[12];
    const float* wr     = (const float*)d_in[13];
    const float* w      = (const float*)d_in[14];
    const float* wt     = (const float*)d_in[15];
    const float* wp     = (const float*)d_in[16];
    const float* wx     = (const float*)d_in[17];
    const float* fc_w   = (const float*)d_in[18];
    const float* fc_b   = (const float*)d_in[19];
    float* out = (float*)d_out;

    float* xwp; cudaGetSymbolAddress((void**)&xwp, g_xwp);
    float* xwh; cudaGetSymbolAddress((void**)&xwh, g_xwh);
    __nv_bfloat16 *embH, *embL, *wihpH, *wihpL, *wihhH, *wihhL, *whhpH, *whhpL, *whhhH, *whhhL;
    cudaGetSymbolAddress((void**)&embH,  c_emb_hi);  cudaGetSymbolAddress((void**)&embL,  c_emb_lo);
    cudaGetSymbolAddress((void**)&wihpH, c_wihp_hi); cudaGetSymbolAddress((void**)&wihpL, c_wihp_lo);
    cudaGetSymbolAddress((void**)&wihhH, c_wihh_hi); cudaGetSymbolAddress((void**)&wihhL, c_wihh_lo);
    cudaGetSymbolAddress((void**)&whhpH, c_whhp_hi); cudaGetSymbolAddress((void**)&whhpL, c_whhp_lo);
    cudaGetSymbolAddress((void**)&whhhH, c_whhh_hi); cudaGetSymbolAddress((void**)&whhhL, c_whhh_lo);

    // ---- weight prep (bf16 hi/lo splits) ----
    {
        long n1 = (long)VV * EEP;
        k_cvt<<<(unsigned)((n1 + 255) / 256), 256>>>(emb, embH, embL, EE, EEP, n1);
        long n2 = (long)G4 * EEP;
        k_cvt<<<(unsigned)((n2 + 255) / 256), 256>>>(w_ih_p, wihpH, wihpL, EE, EEP, n2);
        k_cvt<<<(unsigned)((n2 + 255) / 256), 256>>>(w_ih_h, wihhH, wihhL, EE, EEP, n2);
        long n3 = (long)G4 * HH;
        k_cvt<<<(unsigned)((n3 + 255) / 256), 256>>>(w_hh_p, whhpH, whhpL, HH, HH, n3);
        k_cvt<<<(unsigned)((n3 + 255) / 256), 256>>>(w_hh_h, whhhH, whhhL, HH, HH, n3);
        k_cvt_t<<<(HH * HH) / 256, 256>>>(wy);
    }

    k_build_lut<<<1, LUT_N>>>();
    k_init<<<512, 256>>>();

    // input-side GEMMs (tensor cores)
    k_mma_embed<<<dim3(G4 / 64, (SPP * BB) / 64), 256>>>(prem, SPP, wihpH, wihpL, b_ih_p, b_hh_p, xwp);
    k_mma_embed<<<dim3(G4 / 64, (SHH * BB) / 64), 256>>>(hyp,  SHH, wihhH, wihhL, b_ih_h, b_hh_h, xwh);

    // premise LSTM (tensor-core fused step, pre-split h)
    for (int t = 0; t < SPP; t++)
        k_mma_lstm<<<dim3(HH / 16, 2), 256>>>(whhpH, whhpL, xwp, prem, SPP, t, 0);
    k_prep_hyp<<<512, 256>>>();

    // hypothesis LSTM
    for (int t = 0; t < SHH; t++)
        k_mma_lstm<<<dim3(HH / 16, 2), 256>>>(whhhH, whhhL, xwh, hyp, SHH, t, 1);

    // first = Y @ wy
    k_mma_first<<<dim3(HH / 64, (SPP * BB) / 64), 256>>>();

    // word-by-word attention scan: 2 kernels / step, one block per batch row in the fused step
    for (int t = 0; t < SHH; t++) {
        k_secondtrt<<<dim3(32, 2), 256>>>(wh, wr, wt, t);
        k_scanstep<<<BB, 512>>>(prem, hyp, w, t);
    }

    k_hstar<<<dim3(32, 2), 256>>>(wp, wx);
    k_logits<<<BB, 256>>>(fc_w, fc_b, out);
}

// round 14
// speedup vs baseline: 1.0099x; 1.0099x over previous
#include <cuda_runtime.h>
#include <cuda_bf16.h>
#include <math.h>
#include <stdint.h>

#define BB   128   // batch
#define SPP  128   // premise seq len
#define SHH  64    // hypothesis seq len
#define HH   1024  // hidden
#define EE   300   // embedding dim
#define EEP  320   // padded embedding K
#define G4   4096  // 4*H
#define VV   50000 // vocab

#define LUT_N    1024
#define LUT_D    (9.5f / 1023.0f)
#define LUT_INVD (1023.0f / 9.5f)

// ---------------- scratch (device globals; no runtime allocation) ----------------
__device__ float g_xwp[(size_t)SPP * BB * G4];
__device__ float g_xwh[(size_t)SHH * BB * G4];
__device__ float g_c[BB * HH];
__device__ float g_cc[BB * HH];
__device__ float g_outp[(size_t)BB * SPP * HH];  // Y, [b][p][h]
__device__ float g_outh[(size_t)SHH * BB * HH];  // [t][b][h]
__device__ float g_first[(size_t)BB * SPP * HH];
__device__ float g_second[BB * HH];
__device__ float g_trt[BB * HH];
__device__ float g_r[BB * HH];
__device__ float g_hstar[BB * HH];
__device__ float2 g_lut[LUT_N];                  // (tanh(i*D), centered slope/index)

// pre-split bf16 LSTM hidden state (ping/pong), written by LSTM epilogue
__device__ __nv_bfloat16 g_hsA_hi[BB * HH];
__device__ __nv_bfloat16 g_hsA_lo[BB * HH];
__device__ __nv_bfloat16 g_hsB_hi[BB * HH];
__device__ __nv_bfloat16 g_hsB_lo[BB * HH];

// pre-split bf16 weights (hi/lo)
__device__ __nv_bfloat16 c_emb_hi[(size_t)VV * EEP];
__device__ __nv_bfloat16 c_emb_lo[(size_t)VV * EEP];
__device__ __nv_bfloat16 c_wihp_hi[(size_t)G4 * EEP];
__device__ __nv_bfloat16 c_wihp_lo[(size_t)G4 * EEP];
__device__ __nv_bfloat16 c_wihh_hi[(size_t)G4 * EEP];
__device__ __nv_bfloat16 c_wihh_lo[(size_t)G4 * EEP];
__device__ __nv_bfloat16 c_whhp_hi[(size_t)G4 * HH];
__device__ __nv_bfloat16 c_whhp_lo[(size_t)G4 * HH];
__device__ __nv_bfloat16 c_whhh_hi[(size_t)G4 * HH];
__device__ __nv_bfloat16 c_whhh_lo[(size_t)G4 * HH];
__device__ __nv_bfloat16 c_wyt_hi[(size_t)HH * HH];   // wy^T: [n][k]
__device__ __nv_bfloat16 c_wyt_lo[(size_t)HH * HH];

// ---------------- helpers ----------------
__device__ __forceinline__ float sigm(float x) { return 1.f / (1.f + expf(-x)); }

// LUT tanh (ONE-SHOT score path ONLY -- never inside a recurrence): |err| ~8e-6
__device__ __forceinline__ float tanh_lut(float x, const float2* lut) {
    float t = fminf(fabsf(x) * LUT_INVD, 1023.0f);
    float m = t + 12582912.0f;                 // 1.5*2^23: RN -> round(t) in mantissa
    int   i = __float_as_int(m) & 0x3FF;
    float fr = t - (m - 12582912.0f);          // [-0.5, 0.5] in index units
    float2 e = lut[i];
    float v = fmaf(fr, e.y, e.x);              // v >= 0 always
    return __int_as_float((__float_as_int(x) & 0x80000000) | __float_as_int(v));
}

__device__ __forceinline__ void mma16816(float4& d, const uint32_t* a, const uint32_t* b) {
    asm volatile(
        "mma.sync.aligned.m16n8k16.row.col.f32.bf16.bf16.f32 "
        "{%0,%1,%2,%3},{%4,%5,%6,%7},{%8,%9},{%0,%1,%2,%3};\n"
        : "+f"(d.x), "+f"(d.y), "+f"(d.z), "+f"(d.w)
        : "r"(a[0]), "r"(a[1]), "r"(a[2]), "r"(a[3]), "r"(b[0]), "r"(b[1]));
}

// convert 8 consecutive fp32 -> packed bf16 hi/lo (4 u32 each)
__device__ __forceinline__ void split_pack8(const float* g, uint32_t* ah, uint32_t* al) {
    float4 v0 = *(const float4*)g, v1 = *(const float4*)(g + 4);
    float f[8] = {v0.x, v0.y, v0.z, v0.w, v1.x, v1.y, v1.z, v1.w};
    #pragma unroll
    for (int i = 0; i < 4; i++) {
        __nv_bfloat16 h0 = __float2bfloat16(f[2*i]);
        __nv_bfloat16 h1 = __float2bfloat16(f[2*i+1]);
        __nv_bfloat162 hh; hh.x = h0; hh.y = h1;
        ah[i] = *(uint32_t*)&hh;
        __nv_bfloat162 ll;
        ll.x = __float2bfloat16(f[2*i]   - __bfloat162float(h0));
        ll.y = __float2bfloat16(f[2*i+1] - __bfloat162float(h1));
        al[i] = *(uint32_t*)&ll;
    }
}

// fragment compute over one 32-k chunk (smem tiles bf16 [64][40])
__device__ __forceinline__ void mma_chunk(
    const __nv_bfloat16* sAh, const __nv_bfloat16* sAl,
    const __nv_bfloat16* sBh, const __nv_bfloat16* sBl,
    int warp_m, int warp_n, int lane, float4 c[2][2])
{
    int grp = lane >> 2, tig = lane & 3;
    #pragma unroll
    for (int ks = 0; ks < 32; ks += 16) {
        uint32_t ah[2][4], al[2][4], bh[2][2], bl[2][2];
        #pragma unroll
        for (int i = 0; i < 2; i++) {
            int r = warp_m * 32 + i * 16 + grp;
            const __nv_bfloat16* ph = sAh + r * 40 + ks + tig * 2;
            const __nv_bfloat16* pl = sAl + r * 40 + ks + tig * 2;
            ah[i][0] = *(const uint32_t*)(ph);
            ah[i][1] = *(const uint32_t*)(ph + 8 * 40);
            ah[i][2] = *(const uint32_t*)(ph + 8);
            ah[i][3] = *(const uint32_t*)(ph + 8 * 40 + 8);
            al[i][0] = *(const uint32_t*)(pl);
            al[i][1] = *(const uint32_t*)(pl + 8 * 40);
            al[i][2] = *(const uint32_t*)(pl + 8);
            al[i][3] = *(const uint32_t*)(pl + 8 * 40 + 8);
        }
        #pragma unroll
        for (int j = 0; j < 2; j++) {
            int n = warp_n * 16 + j * 8 + grp;
            const __nv_bfloat16* ph = sBh + n * 40 + ks + tig * 2;
            const __nv_bfloat16* pl = sBl + n * 40 + ks + tig * 2;
            bh[j][0] = *(const uint32_t*)(ph);
            bh[j][1] = *(const uint32_t*)(ph + 8);
            bl[j][0] = *(const uint32_t*)(pl);
            bl[j][1] = *(const uint32_t*)(pl + 8);
        }
        #pragma unroll
        for (int i = 0; i < 2; i++)
            #pragma unroll
            for (int j = 0; j < 2; j++) {
                mma16816(c[i][j], ah[i], bh[j]);
                mma16816(c[i][j], ah[i], bl[j]);
                mma16816(c[i][j], al[i], bh[j]);
            }
    }
}

// ---------------- weight prep: fp32 -> bf16 hi/lo (with K padding) ----------------
__global__ void k_cvt(const float* __restrict__ src, __nv_bfloat16* __restrict__ hi,
                      __nv_bfloat16* __restrict__ lo, int C, int Cp, long total)
{
    long idx = (long)blockIdx.x * blockDim.x + threadIdx.x;
    if (idx >= total) return;
    long r = idx / Cp; int cc = (int)(idx % Cp);
    float v = (cc < C) ? src[r * C + cc] : 0.f;
    __nv_bfloat16 h = __float2bfloat16(v);
    hi[idx] = h;
    lo[idx] = __float2bfloat16(v - __bfloat162float(h));
}
__global__ void k_cvt_t(const float* __restrict__ src)  // wy [K][N] -> [n][k]
{
    int idx = blockIdx.x * blockDim.x + threadIdx.x;   // n*HH + k
    int n = idx >> 10, k = idx & 1023;
    float v = src[(size_t)k * HH + n];
    __nv_bfloat16 h = __float2bfloat16(v);
    c_wyt_hi[idx] = h;
    c_wyt_lo[idx] = __float2bfloat16(v - __bfloat162float(h));
}

// ---------------- init (state + LUT fused) ----------------
__global__ void k_initlut() {
    int i = blockIdx.x * blockDim.x + threadIdx.x;
    if (i < LUT_N) {
        float v  = tanhf(i * LUT_D);
        float vp = tanhf((i + 1) * LUT_D);
        float vm = tanhf((i - 1) * LUT_D);
        g_lut[i] = make_float2(v, (vp - vm) * 0.5f);
    }
    if (i < BB * HH) {
        g_c[i] = 0.f; g_cc[i] = 0.f; g_r[i] = 0.f;
        __nv_bfloat16 z = __float2bfloat16(0.f);
        g_hsA_hi[i] = z; g_hsA_lo[i] = z;
        g_hsB_hi[i] = z; g_hsB_lo[i] = z;
    }
}
__global__ void k_prep_hyp() {   // h0 = 0 (parity-0 split buffers), c0 = masked last premise cell
    int i = blockIdx.x * blockDim.x + threadIdx.x;
    if (i < BB * HH) {
        g_c[i] = g_cc[i];
        __nv_bfloat16 z = __float2bfloat16(0.f);
        g_hsA_hi[i] = z; g_hsA_lo[i] = z;
    }
}

// ---------------- mma embed: out = gather(emb)[M x K] @ wih^T + biases ----------------
__global__ void __launch_bounds__(256) k_mma_embed(
    const int* __restrict__ toks, int S,
    const __nv_bfloat16* __restrict__ Bhi, const __nv_bfloat16* __restrict__ Blo,
    const float* __restrict__ bih, const float* __restrict__ bhh, float* __restrict__ outp)
{
    __shared__ __nv_bfloat16 sAh[64*40], sAl[64*40], sBh[64*40], sBl[64*40];
    __shared__ int stok[64];
    int tid = threadIdx.x, lane = tid & 31, wid = tid >> 5;
    int warp_m = wid >> 2, warp_n = wid & 3;
    int m0 = blockIdx.y * 64, n0 = blockIdx.x * 64;
    if (tid < 64) { int m = m0 + tid; stok[tid] = toks[(m & (BB-1)) * S + (m >> 7)]; }
    __syncthreads();

    int srow = tid >> 2, skq = (tid & 3) * 8;
    const __nv_bfloat16* arow_hi;
    const __nv_bfloat16* arow_lo;
    {
        size_t base = (size_t)stok[srow] * EEP;
        arow_hi = c_emb_hi + base; arow_lo = c_emb_lo + base;
    }
    size_t bbase = (size_t)(n0 + srow) * EEP;

    float4 c[2][2] = {};
    uint4 pAh, pAl, pBh, pBl;
    pAh = *(const uint4*)(arow_hi + skq);
    pAl = *(const uint4*)(arow_lo + skq);
    pBh = *(const uint4*)(Bhi + bbase + skq);
    pBl = *(const uint4*)(Blo + bbase + skq);

    const int KC = EEP / 32;
    for (int ck = 0; ck < KC; ck++) {
        *(uint4*)&sAh[srow*40 + skq] = pAh;
        *(uint4*)&sAl[srow*40 + skq] = pAl;
        *(uint4*)&sBh[srow*40 + skq] = pBh;
        *(uint4*)&sBl[srow*40 + skq] = pBl;
        __syncthreads();
        if (ck + 1 < KC) {
            int k0 = (ck + 1) * 32;
            pAh = *(const uint4*)(arow_hi + k0 + skq);
            pAl = *(const uint4*)(arow_lo + k0 + skq);
            pBh = *(const uint4*)(Bhi + bbase + k0 + skq);
            pBl = *(const uint4*)(Blo + bbase + k0 + skq);
        }
        mma_chunk(sAh, sAl, sBh, sBl, warp_m, warp_n, lane, c);
        __syncthreads();
    }

    int grp = lane >> 2, tig = lane & 3;
    #pragma unroll
    for (int i = 0; i < 2; i++) {
        int r = m0 + warp_m * 32 + i * 16 + grp;
        #pragma unroll
        for (int j = 0; j < 2; j++) {
            int n = n0 + warp_n * 16 + j * 8 + tig * 2;
            float b0 = bih[n] + bhh[n], b1 = bih[n+1] + bhh[n+1];
            outp[(size_t)r * G4 + n]       = c[i][j].x + b0;
            outp[(size_t)r * G4 + n + 1]   = c[i][j].y + b1;
            outp[(size_t)(r+8) * G4 + n]   = c[i][j].z + b0;
            outp[(size_t)(r+8) * G4 + n+1] = c[i][j].w + b1;
        }
    }
}

// ---------------- mma first: g_first = g_outp @ wy ----------------
__global__ void __launch_bounds__(256) k_mma_first()
{
    __shared__ __nv_bfloat16 sAh[64*40], sAl[64*40], sBh[64*40], sBl[64*40];
    int tid = threadIdx.x, lane = tid & 31, wid = tid >> 5;
    int warp_m = wid >> 2, warp_n = wid & 3;
    int m0 = blockIdx.y * 64, n0 = blockIdx.x * 64;

    int srow = tid >> 2, skq = (tid & 3) * 8;
    const float* arow = g_outp + (size_t)(m0 + srow) * HH;
    size_t bbase = (size_t)(n0 + srow) * HH;

    float4 c[2][2] = {};
    uint32_t pAh[4], pAl[4]; uint4 pBh, pBl;
    split_pack8(arow + skq, pAh, pAl);
    pBh = *(const uint4*)(c_wyt_hi + bbase + skq);
    pBl = *(const uint4*)(c_wyt_lo + bbase + skq);

    const int KC = HH / 32;
    for (int ck = 0; ck < KC; ck++) {
        *(uint4*)&sAh[srow*40 + skq] = make_uint4(pAh[0], pAh[1], pAh[2], pAh[3]);
        *(uint4*)&sAl[srow*40 + skq] = make_uint4(pAl[0], pAl[1], pAl[2], pAl[3]);
        *(uint4*)&sBh[srow*40 + skq] = pBh;
        *(uint4*)&sBl[srow*40 + skq] = pBl;
        __syncthreads();
        if (ck + 1 < KC) {
            int k0 = (ck + 1) * 32;
            split_pack8(arow + k0 + skq, pAh, pAl);
            pBh = *(const uint4*)(c_wyt_hi + bbase + k0 + skq);
            pBl = *(const uint4*)(c_wyt_lo + bbase + k0 + skq);
        }
        mma_chunk(sAh, sAl, sBh, sBl, warp_m, warp_n, lane, c);
        __syncthreads();
    }

    int grp = lane >> 2, tig = lane & 3;
    #pragma unroll
    for (int i = 0; i < 2; i++) {
        int r = m0 + warp_m * 32 + i * 16 + grp;
        #pragma unroll
        for (int j = 0; j < 2; j++) {
            int n = n0 + warp_n * 16 + j * 8 + tig * 2;
            g_first[(size_t)r * HH + n]       = c[i][j].x;
            g_first[(size_t)r * HH + n + 1]   = c[i][j].y;
            g_first[(size_t)(r+8) * HH + n]   = c[i][j].z;
            g_first[(size_t)(r+8) * HH + n+1] = c[i][j].w;
        }
    }
}

// ---------------- mma LSTM step (fused pointwise, pre-split h, EXACT activations) ----------------
// Block: 64 batch x (16 h-cols x 4 gates). Grid: dim3(HH/16=64, 2).
__global__ void __launch_bounds__(256) k_mma_lstm(
    const __nv_bfloat16* __restrict__ Whi, const __nv_bfloat16* __restrict__ Wlo,
    const float* __restrict__ xw, const int* __restrict__ toks, int S, int t, int which)
{
    const __nv_bfloat16* hin_hi = (t & 1) ? g_hsB_hi : g_hsA_hi;
    const __nv_bfloat16* hin_lo = (t & 1) ? g_hsB_lo : g_hsA_lo;
    __nv_bfloat16* hout_hi = (t & 1) ? g_hsA_hi : g_hsB_hi;
    __nv_bfloat16* hout_lo = (t & 1) ? g_hsA_lo : g_hsB_lo;

    __shared__ __align__(16) char pool[64*40*2*4 + 64*68*4];
    __nv_bfloat16* sAh = (__nv_bfloat16*)pool;
    __nv_bfloat16* sAl = sAh + 64*40;
    __nv_bfloat16* sBh = sAl + 64*40;
    __nv_bfloat16* sBl = sBh + 64*40;
    float* Gs = (float*)(pool + 64*40*2*4);   // [64][68]

    int tid = threadIdx.x, lane = tid & 31, wid = tid >> 5;
    int warp_m = wid >> 2, warp_n = wid & 3;
    int m0 = blockIdx.y * 64;        // batch offset
    int h0 = blockIdx.x * 16;        // h-col offset

    int srow = tid >> 2, skq = (tid & 3) * 8;
    const __nv_bfloat16* arow_hi = hin_hi + (size_t)(m0 + srow) * HH;
    const __nv_bfloat16* arow_lo = hin_lo + (size_t)(m0 + srow) * HH;
    int gate = srow >> 4, hh = srow & 15;
    size_t bbase = (size_t)(gate * HH + h0 + hh) * HH;

    float4 c[2][2] = {};
    uint4 pAh, pAl, pBh, pBl;
    pAh = *(const uint4*)(arow_hi + skq);
    pAl = *(const uint4*)(arow_lo + skq);
    pBh = *(const uint4*)(Whi + bbase + skq);
    pBl = *(const uint4*)(Wlo + bbase + skq);

    const int KC = HH / 32;
    for (int ck = 0; ck < KC; ck++) {
        *(uint4*)&sAh[srow*40 + skq] = pAh;
        *(uint4*)&sAl[srow*40 + skq] = pAl;
        *(uint4*)&sBh[srow*40 + skq] = pBh;
        *(uint4*)&sBl[srow*40 + skq] = pBl;
        __syncthreads();
        if (ck + 1 < KC) {
            int k0 = (ck + 1) * 32;
            pAh = *(const uint4*)(arow_hi + k0 + skq);
            pAl = *(const uint4*)(arow_lo + k0 + skq);
            pBh = *(const uint4*)(Whi + bbase + k0 + skq);
            pBl = *(const uint4*)(Wlo + bbase + k0 + skq);
        }
        mma_chunk(sAh, sAl, sBh, sBl, warp_m, warp_n, lane, c);
        __syncthreads();
    }

    // gate preactivations -> Gs[batch64][col = gate*16 + hh]
    {
        int grp = lane >> 2, tig = lane & 3;
        #pragma unroll
        for (int i = 0; i < 2; i++) {
            int r = warp_m * 32 + i * 16 + grp;
            #pragma unroll
            for (int j = 0; j < 2; j++) {
                int n = warp_n * 16 + j * 8 + tig * 2;
                Gs[r * 68 + n]         = c[i][j].x;
                Gs[r * 68 + n + 1]     = c[i][j].y;
                Gs[(r+8) * 68 + n]     = c[i][j].z;
                Gs[(r+8) * 68 + n + 1] = c[i][j].w;
            }
        }
    }
    __syncthreads();

    // pointwise: EXACT activations (recurrence must not take approximation error)
    {
        int q = tid * 4;
        int b64 = q >> 4, hh4 = q & 15;
        int b = m0 + b64;
        int h = h0 + hh4;
        float m = (toks[b * S + t] != 0) ? 1.f : 0.f;
        float im = 1.f - m;
        const float* xr = xw + ((size_t)t * BB + b) * G4 + h;
        float4 gi = *(float4*)&Gs[b64 * 68 +  0 + hh4];
        float4 gf = *(float4*)&Gs[b64 * 68 + 16 + hh4];
        float4 gg = *(float4*)&Gs[b64 * 68 + 32 + hh4];
        float4 go = *(float4*)&Gs[b64 * 68 + 48 + hh4];
        float4 xi = *(const float4*)&xr[0 * HH];
        float4 xf = *(const float4*)&xr[1 * HH];
        float4 xg = *(const float4*)&xr[2 * HH];
        float4 xo = *(const float4*)&xr[3 * HH];
        float4 cc = *(float4*)&g_c[b * HH + h];
        float giv[4] = {gi.x + xi.x, gi.y + xi.y, gi.z + xi.z, gi.w + xi.w};
        float gfv[4] = {gf.x + xf.x, gf.y + xf.y, gf.z + xf.z, gf.w + xf.w};
        float ggv[4] = {gg.x + xg.x, gg.y + xg.y, gg.z + xg.z, gg.w + xg.w};
        float gov[4] = {go.x + xo.x, go.y + xo.y, go.z + xo.z, go.w + xo.w};
        float cv[4] = {cc.x, cc.y, cc.z, cc.w};
        float c2v[4], h2v[4];
        #pragma unroll
        for (int i = 0; i < 4; i++) {
            float iv = sigm(giv[i]), fv = sigm(gfv[i]);
            float gv = tanhf(ggv[i]), ov = sigm(gov[i]);
            float c2 = fv * cv[i] + iv * gv;
            c2v[i] = c2;
            h2v[i] = ov * tanhf(c2);
        }
        float4 c2f = make_float4(c2v[0], c2v[1], c2v[2], c2v[3]);
        float4 h2f = make_float4(h2v[0], h2v[1], h2v[2], h2v[3]);
        *(float4*)&g_c[b * HH + h] = c2f;

        // write raw h as bf16 hi/lo split (next step's A operand)
        {
            __nv_bfloat162 hi01, hi23, lo01, lo23;
            hi01.x = __float2bfloat16(h2v[0]); hi01.y = __float2bfloat16(h2v[1]);
            hi23.x = __float2bfloat16(h2v[2]); hi23.y = __float2bfloat16(h2v[3]);
            lo01.x = __float2bfloat16(h2v[0] - __bfloat162float(hi01.x));
            lo01.y = __float2bfloat16(h2v[1] - __bfloat162float(hi01.y));
            lo23.x = __float2bfloat16(h2v[2] - __bfloat162float(hi23.x));
            lo23.y = __float2bfloat16(h2v[3] - __bfloat162float(hi23.y));
            uint2 phi = make_uint2(*(uint32_t*)&hi01, *(uint32_t*)&hi23);
            uint2 plo = make_uint2(*(uint32_t*)&lo01, *(uint32_t*)&lo23);
            *(uint2*)&hout_hi[b * HH + h] = phi;
            *(uint2*)&hout_lo[b * HH + h] = plo;
        }

        if (which == 0) {
            float4 prev = make_float4(0.f, 0.f, 0.f, 0.f);
            if (t > 0) prev = *(float4*)&g_outp[((size_t)b * SPP + (t - 1)) * HH + h];
            *(float4*)&g_outp[((size_t)b * SPP + t) * HH + h] = make_float4(
                m * h2f.x + im * prev.x, m * h2f.y + im * prev.y,
                m * h2f.z + im * prev.z, m * h2f.w + im * prev.w);
            float4 pc = *(float4*)&g_cc[b * HH + h];
            *(float4*)&g_cc[b * HH + h] = make_float4(
                m * c2f.x + im * pc.x, m * c2f.y + im * pc.y,
                m * c2f.z + im * pc.z, m * c2f.w + im * pc.w);
        } else {
            float4 prev = make_float4(0.f, 0.f, 0.f, 0.f);
            if (t > 0) prev = *(float4*)&g_outh[((size_t)(t - 1) * BB + b) * HH + h];
            *(float4*)&g_outh[((size_t)t * BB + b) * HH + h] = make_float4(
                m * h2f.x + im * prev.x, m * h2f.y + im * prev.y,
                m * h2f.z + im * prev.z, m * h2f.w + im * prev.w);
        }
    }
}

// ---------------- fused second + trt (fp32 SIMT) ----------------
__global__ void __launch_bounds__(256) k_secondtrt(
    const float* __restrict__ wh_, const float* __restrict__ wr_,
    const float* __restrict__ wt_, int t)
{
    __shared__ float As1[32][68];   // outh_t
    __shared__ float As2[32][68];   // r
    __shared__ float Bs1[32][36];
    __shared__ float Bs2[32][36];
    __shared__ float Bs3[32][36];
    const float* A1 = g_outh + (size_t)t * BB * HH;
    const int K = HH, N = HH;
    int tid = threadIdx.x;
    int n0 = blockIdx.x * 32, m0 = blockIdx.y * 64;
    int ty = tid / 8, tx = tid % 8;
    int alm = tid / 4, alk = (tid % 4) * 8;
    float acc1[2][4] = {};
    float acc2[2][4] = {};

    for (int k0 = 0; k0 < K; k0 += 32) {
        {
            const float4* ap = (const float4*)&A1[(size_t)(m0 + alm) * K + k0 + alk];
            float4 v0 = ap[0], v1 = ap[1];
            As1[alk + 0][alm] = v0.x; As1[alk + 1][alm] = v0.y; As1[alk + 2][alm] = v0.z; As1[alk + 3][alm] = v0.w;
            As1[alk + 4][alm] = v1.x; As1[alk + 5][alm] = v1.y; As1[alk + 6][alm] = v1.z; As1[alk + 7][alm] = v1.w;
        }
        {
            const float4* ap = (const float4*)&g_r[(size_t)(m0 + alm) * K + k0 + alk];
            float4 v0 = ap[0], v1 = ap[1];
            As2[alk + 0][alm] = v0.x; As2[alk + 1][alm] = v0.y; As2[alk + 2][alm] = v0.z; As2[alk + 3][alm] = v0.w;
            As2[alk + 4][alm] = v1.x; As2[alk + 5][alm] = v1.y; As2[alk + 6][alm] = v1.z; As2[alk + 7][alm] = v1.w;
        }
        {
            int bk = tid / 8, bn = (tid % 8) * 4;
            *(float4*)&Bs1[bk][bn] = *(const float4*)&wh_[(size_t)(k0 + bk) * N + n0 + bn];
            *(float4*)&Bs2[bk][bn] = *(const float4*)&wr_[(size_t)(k0 + bk) * N + n0 + bn];
            *(float4*)&Bs3[bk][bn] = *(const float4*)&wt_[(size_t)(k0 + bk) * N + n0 + bn];
        }
        __syncthreads();
        #pragma unroll
        for (int k = 0; k < 32; k++) {
            float a0 = As1[k][ty * 2 + 0], a1 = As1[k][ty * 2 + 1];
            float c0 = As2[k][ty * 2 + 0], c1 = As2[k][ty * 2 + 1];
            float4 b1 = *(const float4*)&Bs1[k][tx * 4];
            float4 b2 = *(const float4*)&Bs2[k][tx * 4];
            float4 b3 = *(const float4*)&Bs3[k][tx * 4];
            acc1[0][0] += a0 * b1.x + c0 * b2.x; acc1[0][1] += a0 * b1.y + c0 * b2.y;
            acc1[0][2] += a0 * b1.z + c0 * b2.z; acc1[0][3] += a0 * b1.w + c0 * b2.w;
            acc1[1][0] += a1 * b1.x + c1 * b2.x; acc1[1][1] += a1 * b1.y + c1 * b2.y;
            acc1[1][2] += a1 * b1.z + c1 * b2.z; acc1[1][3] += a1 * b1.w + c1 * b2.w;
            acc2[0][0] += c0 * b3.x; acc2[0][1] += c0 * b3.y; acc2[0][2] += c0 * b3.z; acc2[0][3] += c0 * b3.w;
            acc2[1][0] += c1 * b3.x; acc2[1][1] += c1 * b3.y; acc2[1][2] += c1 * b3.z; acc2[1][3] += c1 * b3.w;
        }
        __syncthreads();
    }
    #pragma unroll
    for (int i = 0; i < 2; i++) {
        int m = m0 + ty * 2 + i;
        #pragma unroll
        for (int j = 0; j < 4; j++) {
            int n = n0 + tx * 4 + j;
            g_second[(size_t)m * HH + n] = acc1[i][j];
            g_trt[(size_t)m * HH + n]    = acc2[i][j];
        }
    }
}

// ---------------- fused scan step: score (LUT) + softmax + r update, one block per b ----------------
__global__ void __launch_bounds__(512) k_scanstep(const int* __restrict__ prem,
                                                  const int* __restrict__ hyp,
                                                  const float* __restrict__ w_, int t)
{
    __shared__ float2 slut[LUT_N];
    __shared__ float ssec[HH];
    __shared__ float sw[HH];
    __shared__ float sc[SPP];
    __shared__ float al[SPP];
    int b = blockIdx.x, tid = threadIdx.x;
    int lane = tid & 31, wid = tid >> 5;

    slut[tid]       = g_lut[tid];
    slut[tid + 512] = g_lut[tid + 512];
    ssec[tid]       = g_second[b * HH + tid];
    ssec[tid + 512] = g_second[b * HH + tid + 512];
    sw[tid]         = w_[tid];
    sw[tid + 512]   = w_[tid + 512];
    __syncthreads();

    // scores: warp w handles p = w*8 .. w*8+7 (LUT tanh: one-shot path, proven safe)
    #pragma unroll 1
    for (int i = 0; i < 8; i++) {
        int p = wid * 8 + i;
        const float4* frow = (const float4*)(g_first + ((size_t)b * SPP + p) * HH);
        float acc = 0.f;
        #pragma unroll
        for (int j = 0; j < 8; j++) {
            int idx = j * 32 + lane;
            float4 f  = frow[idx];
            float4 s  = *(const float4*)&ssec[idx * 4];
            float4 ww = *(const float4*)&sw[idx * 4];
            acc += tanh_lut(f.x + s.x, slut) * ww.x + tanh_lut(f.y + s.y, slut) * ww.y
                 + tanh_lut(f.z + s.z, slut) * ww.z + tanh_lut(f.w + s.w, slut) * ww.w;
        }
        #pragma unroll
        for (int o = 16; o > 0; o >>= 1) acc += __shfl_down_sync(0xffffffffu, acc, o);
        if (lane == 0)
            sc[p] = acc + ((prem[b * SPP + p] != 0) ? 0.f : -1000.f);
    }
    __syncthreads();

    // softmax by warp 0
    if (wid == 0) {
        float v0 = sc[lane], v1 = sc[lane+32], v2 = sc[lane+64], v3 = sc[lane+96];
        float mx = fmaxf(fmaxf(v0, v1), fmaxf(v2, v3));
        #pragma unroll
        for (int o = 16; o > 0; o >>= 1) mx = fmaxf(mx, __shfl_xor_sync(0xffffffffu, mx, o));
        float e0 = expf(v0-mx), e1 = expf(v1-mx), e2 = expf(v2-mx), e3 = expf(v3-mx);
        float ss = e0 + e1 + e2 + e3;
        #pragma unroll
        for (int o = 16; o > 0; o >>= 1) ss += __shfl_xor_sync(0xffffffffu, ss, o);
        float inv = 1.f / ss;
        al[lane]    = e0 * inv; al[lane+32] = e1 * inv;
        al[lane+64] = e2 * inv; al[lane+96] = e3 * inv;
    }
    __syncthreads();

    // r update: r_t[h] = sum_p al[p]*Y[b][p][h] + tanh(trt); mask-carry
    // EXACT tanhf here -- this feeds the 64-step r recurrence (LUT here caused the
    // R10/R12 1.5e-3 failures; approximation error compounds through wr/wt).
    {
        int h = tid * 2;
        const float* yb = g_outp + (size_t)b * SPP * HH + h;
        float ax = 0.f, ay = 0.f;
        #pragma unroll 4
        for (int p = 0; p < SPP; p++) {
            float a = al[p];
            float2 y = *(const float2*)&yb[(size_t)p * HH];
            ax += a * y.x; ay += a * y.y;
        }
        float2 tr = *(const float2*)&g_trt[b * HH + h];
        float rt0 = ax + tanhf(tr.x);
        float rt1 = ay + tanhf(tr.y);
        float m = (hyp[b * SHH + t] != 0) ? 1.f : 0.f;
        float im = 1.f - m;
        float2 r = *(float2*)&g_r[b * HH + h];
        *(float2*)&g_r[b * HH + h] = make_float2(m * rt0 + im * r.x, m * rt1 + im * r.y);
    }
}

// ---------------- small-M fp32 GEMM (h_star) ----------------
__global__ void __launch_bounds__(256) k_hstar(const float* __restrict__ wp_, const float* __restrict__ wx_)
{
    __shared__ float As1[32][68];
    __shared__ float As2[32][68];
    __shared__ float Bs1[32][36];
    __shared__ float Bs2[32][36];
    const float* A1 = g_r;
    const float* A2 = g_outh + (size_t)(SHH - 1) * BB * HH;
    const int K = HH, N = HH;
    int tid = threadIdx.x;
    int n0 = blockIdx.x * 32, m0 = blockIdx.y * 64;
    int ty = tid / 8, tx = tid % 8;
    int alm = tid / 4, alk = (tid % 4) * 8;
    float acc[2][4] = {};

    for (int k0 = 0; k0 < K; k0 += 32) {
        {
            const float4* ap = (const float4*)&A1[(size_t)(m0 + alm) * K + k0 + alk];
            float4 v0 = ap[0], v1 = ap[1];
            As1[alk + 0][alm] = v0.x; As1[alk + 1][alm] = v0.y; As1[alk + 2][alm] = v0.z; As1[alk + 3][alm] = v0.w;
            As1[alk + 4][alm] = v1.x; As1[alk + 5][alm] = v1.y; As1[alk + 6][alm] = v1.z; As1[alk + 7][alm] = v1.w;
        }
        {
            const float4* ap = (const float4*)&A2[(size_t)(m0 + alm) * K + k0 + alk];
            float4 v0 = ap[0], v1 = ap[1];
            As2[alk + 0][alm] = v0.x; As2[alk + 1][alm] = v0.y; As2[alk + 2][alm] = v0.z; As2[alk + 3][alm] = v0.w;
            As2[alk + 4][alm] = v1.x; As2[alk + 5][alm] = v1.y; As2[alk + 6][alm] = v1.z; As2[alk + 7][alm] = v1.w;
        }
        {
            int bk = tid / 8, bn = (tid % 8) * 4;
            *(float4*)&Bs1[bk][bn] = *(const float4*)&wp_[(size_t)(k0 + bk) * N + n0 + bn];
            *(float4*)&Bs2[bk][bn] = *(const float4*)&wx_[(size_t)(k0 + bk) * N + n0 + bn];
        }
        __syncthreads();
        #pragma unroll
        for (int k = 0; k < 32; k++) {
            float a0 = As1[k][ty * 2 + 0], a1 = As1[k][ty * 2 + 1];
            float c0 = As2[k][ty * 2 + 0], c1 = As2[k][ty * 2 + 1];
            float4 b = *(const float4*)&Bs1[k][tx * 4];
            float4 d = *(const float4*)&Bs2[k][tx * 4];
            acc[0][0] += a0 * b.x + c0 * d.x; acc[0][1] += a0 * b.y + c0 * d.y;
            acc[0][2] += a0 * b.z + c0 * d.z; acc[0][3] += a0 * b.w + c0 * d.w;
            acc[1][0] += a1 * b.x + c1 * d.x; acc[1][1] += a1 * b.y + c1 * d.y;
            acc[1][2] += a1 * b.z + c1 * d.z; acc[1][3] += a1 * b.w + c1 * d.w;
        }
        __syncthreads();
    }
    #pragma unroll
    for (int i = 0; i < 2; i++) {
        int m = m0 + ty * 2 + i;
        #pragma unroll
        for (int j = 0; j < 4; j++)
            g_hstar[(size_t)m * N + n0 + tx * 4 + j] = acc[i][j];
    }
}

// ---------------- logits + final softmax ----------------
__global__ void __launch_bounds__(256) k_logits(const float* __restrict__ fcw,
                                                const float* __restrict__ fcb,
                                                float* __restrict__ out)
{
    int b = blockIdx.x, tid = threadIdx.x;
    float a0 = 0.f, a1 = 0.f, a2 = 0.f, a3 = 0.f;
    for (int h = tid; h < HH; h += 256) {
        float hs = tanhf(g_hstar[b * HH + h]);
        a0 += hs * fcw[0 * HH + h];
        a1 += hs * fcw[1 * HH + h];
        a2 += hs * fcw[2 * HH + h];
        a3 += hs * fcw[3 * HH + h];
    }
    __shared__ float sm[4][256];
    sm[0][tid] = a0; sm[1][tid] = a1; sm[2][tid] = a2; sm[3][tid] = a3;
    __syncthreads();
    for (int s = 128; s > 0; s >>= 1) {
        if (tid < s) {
            #pragma unroll
            for (int c = 0; c < 4; c++) sm[c][tid] += sm[c][tid + s];
        }
        __syncthreads();
    }
    if (tid == 0) {
        float l[4]; float mx = -1e30f;
        #pragma unroll
        for (int c = 0; c < 4; c++) { l[c] = sm[c][0] + fcb[c]; mx = fmaxf(mx, l[c]); }
        float s = 0.f;
        #pragma unroll
        for (int c = 0; c < 4; c++) { l[c] = expf(l[c] - mx); s += l[c]; }
        #pragma unroll
        for (int c = 0; c < 4; c++) out[b * 4 + c] = l[c] / s;
    }
}

// ---------------- launch ----------------
extern "C" void kernel_launch(void* const* d_in, const int* in_sizes, int n_in,
                              void* d_out, int out_size)
{
    (void)in_sizes; (void)n_in; (void)out_size;
    const int*   prem   = (const int*)d_in[0];
    const int*   hyp    = (const int*)d_in[1];
    const float* emb    = (const float*)d_in[2];
    const float* w_ih_p = (const float*)d_in[3];
    const float* w_hh_p = (const float*)d_in[4];
    const float* b_ih_p = (const float*)d_in[5];
    const float* b_hh_p = (const float*)d_in[6];
    const float* w_ih_h = (const float*)d_in[7];
    const float* w_hh_h = (const float*)d_in[8];
    const float* b_ih_h = (const float*)d_in[9];
    const float* b_hh_h = (const float*)d_in[10];
    const float* wy     = (const float*)d_in[11];
    const float* wh     = (const float*)d_in[12];
    const float* wr     = (const float*)d_in[13];
    const float* w      = (const float*)d_in[14];
    const float* wt     = (const float*)d_in[15];
    const float* wp     = (const float*)d_in[16];
    const float* wx     = (const float*)d_in[17];
    const float* fc_w   = (const float*)d_in[18];
    const float* fc_b   = (const float*)d_in[19];
    float* out = (float*)d_out;

    float* xwp; cudaGetSymbolAddress((void**)&xwp, g_xwp);
    float* xwh; cudaGetSymbolAddress((void**)&xwh, g_xwh);
    __nv_bfloat16 *embH, *embL, *wihpH, *wihpL, *wihhH, *wihhL, *whhpH, *whhpL, *whhhH, *whhhL;
    cudaGetSymbolAddress((void**)&embH,  c_emb_hi);  cudaGetSymbolAddress((void**)&embL,  c_emb_lo);
    cudaGetSymbolAddress((void**)&wihpH, c_wihp_hi); cudaGetSymbolAddress((void**)&wihpL, c_wihp_lo);
    cudaGetSymbolAddress((void**)&wihhH, c_wihh_hi); cudaGetSymbolAddress((void**)&wihhL, c_wihh_lo);
    cudaGetSymbolAddress((void**)&whhpH, c_whhp_hi); cudaGetSymbolAddress((void**)&whhpL, c_whhp_lo);
    cudaGetSymbolAddress((void**)&whhhH, c_whhh_hi); cudaGetSymbolAddress((void**)&whhhL, c_whhh_lo);

    // ---- prep, ordered so launch index 5 (ncu -s 5 -c 1) is the first k_mma_lstm ----
    long n1 = (long)VV * EEP;
    long n2 = (long)G4 * EEP;
    long n3 = (long)G4 * HH;
    k_cvt<<<(unsigned)((n1 + 255) / 256), 256>>>(emb, embH, embL, EE, EEP, n1);        // 0
    k_cvt<<<(unsigned)((n2 + 255) / 256), 256>>>(w_ih_p, wihpH, wihpL, EE, EEP, n2);   // 1
    k_cvt<<<(unsigned)((n3 + 255) / 256), 256>>>(w_hh_p, whhpH, whhpL, HH, HH, n3);    // 2
    k_initlut<<<512, 256>>>();                                                          // 3
    k_mma_embed<<<dim3(G4 / 64, (SPP * BB) / 64), 256>>>(prem, SPP, wihpH, wihpL, b_ih_p, b_hh_p, xwp); // 4

    // premise LSTM (launch 5 = t=0 -> ncu capture target)
    for (int t = 0; t < SPP; t++)
        k_mma_lstm<<<dim3(HH / 16, 2), 256>>>(whhpH, whhpL, xwp, prem, SPP, t, 0);

    // deferred hyp-side prep (independent of premise LSTM)
    k_cvt<<<(unsigned)((n2 + 255) / 256), 256>>>(w_ih_h, wihhH, wihhL, EE, EEP, n2);
    k_cvt<<<(unsigned)((n3 + 255) / 256), 256>>>(w_hh_h, whhhH, whhhL, HH, HH, n3);
    k_cvt_t<<<(HH * HH) / 256, 256>>>(wy);
    k_mma_embed<<<dim3(G4 / 64, (SHH * BB) / 64), 256>>>(hyp, SHH, wihhH, wihhL, b_ih_h, b_hh_h, xwh);
    k_prep_hyp<<<512, 256>>>();

    // hypothesis LSTM
    for (int t = 0; t < SHH; t++)
        k_mma_lstm<<<dim3(HH / 16, 2), 256>>>(whhhH, whhhL, xwh, hyp, SHH, t, 1);

    // first = Y @ wy
    k_mma_first<<<dim3(HH / 64, (SPP * BB) / 64), 256>>>();

    // word-by-word attention scan
    for (int t = 0; t < SHH; t++) {
        k_secondtrt<<<dim3(32, 2), 256>>>(wh, wr, wt, t);
        k_scanstep<<<BB, 512>>>(prem, hyp, w, t);
    }

    k_hstar<<<dim3(32, 2), 256>>>(wp, wx);
    k_logits<<<BB, 256>>>(fc_w, fc_b, out);
}

// round 15
// speedup vs baseline: 1.1837x; 1.1721x over previous
#include <cuda_runtime.h>
#include <cuda_bf16.h>
#include <math.h>
#include <stdint.h>

#define BB   128   // batch
#define SPP  128   // premise seq len
#define SHH  64    // hypothesis seq len
#define HH   1024  // hidden
#define EE   300   // embedding dim
#define EEP  320   // padded embedding K
#define G4   4096  // 4*H
#define VV   50000 // vocab

#define LUT_N    1024
#define LUT_D    (9.5f / 1023.0f)
#define LUT_INVD (1023.0f / 9.5f)

// ---------------- scratch (device globals; no runtime allocation) ----------------
__device__ float g_xwp[(size_t)SPP * BB * G4];
__device__ float g_xwh[(size_t)SHH * BB * G4];
__device__ float g_c[BB * HH];
__device__ float g_cc[BB * HH];
__device__ float g_outp[(size_t)BB * SPP * HH];  // Y, [b][p][h]
__device__ float g_outh[(size_t)SHH * BB * HH];  // [t][b][h]
__device__ float g_first[(size_t)BB * SPP * HH];
__device__ float g_second[BB * HH];
__device__ float g_trt[BB * HH];
__device__ float g_r[BB * HH];
__device__ float g_hstar[BB * HH];
__device__ float2 g_lut[LUT_N];                  // (tanh(i*D), centered slope/index)

// pre-split bf16 LSTM hidden state (ping/pong), written by LSTM epilogue
__device__ __nv_bfloat16 g_hsA_hi[BB * HH];
__device__ __nv_bfloat16 g_hsA_lo[BB * HH];
__device__ __nv_bfloat16 g_hsB_hi[BB * HH];
__device__ __nv_bfloat16 g_hsB_lo[BB * HH];

// pre-split bf16 weights (hi/lo)
__device__ __nv_bfloat16 c_emb_hi[(size_t)VV * EEP];
__device__ __nv_bfloat16 c_emb_lo[(size_t)VV * EEP];
__device__ __nv_bfloat16 c_wihp_hi[(size_t)G4 * EEP];
__device__ __nv_bfloat16 c_wihp_lo[(size_t)G4 * EEP];
__device__ __nv_bfloat16 c_wihh_hi[(size_t)G4 * EEP];
__device__ __nv_bfloat16 c_wihh_lo[(size_t)G4 * EEP];
__device__ __nv_bfloat16 c_whhp_hi[(size_t)G4 * HH];
__device__ __nv_bfloat16 c_whhp_lo[(size_t)G4 * HH];
__device__ __nv_bfloat16 c_whhh_hi[(size_t)G4 * HH];
__device__ __nv_bfloat16 c_whhh_lo[(size_t)G4 * HH];
__device__ __nv_bfloat16 c_wyt_hi[(size_t)HH * HH];   // wy^T: [n][k]
__device__ __nv_bfloat16 c_wyt_lo[(size_t)HH * HH];

// ---------------- helpers ----------------
__device__ __forceinline__ float sigm(float x) { return 1.f / (1.f + expf(-x)); }

// LUT tanh (ONE-SHOT score path ONLY -- never inside a recurrence): |err| ~8e-6
__device__ __forceinline__ float tanh_lut(float x, const float2* lut) {
    float t = fminf(fabsf(x) * LUT_INVD, 1023.0f);
    float m = t + 12582912.0f;                 // 1.5*2^23: RN -> round(t) in mantissa
    int   i = __float_as_int(m) & 0x3FF;
    float fr = t - (m - 12582912.0f);          // [-0.5, 0.5] in index units
    float2 e = lut[i];
    float v = fmaf(fr, e.y, e.x);              // v >= 0 always
    return __int_as_float((__float_as_int(x) & 0x80000000) | __float_as_int(v));
}

__device__ __forceinline__ void mma16816(float4& d, const uint32_t* a, const uint32_t* b) {
    asm volatile(
        "mma.sync.aligned.m16n8k16.row.col.f32.bf16.bf16.f32 "
        "{%0,%1,%2,%3},{%4,%5,%6,%7},{%8,%9},{%0,%1,%2,%3};\n"
        : "+f"(d.x), "+f"(d.y), "+f"(d.z), "+f"(d.w)
        : "r"(a[0]), "r"(a[1]), "r"(a[2]), "r"(a[3]), "r"(b[0]), "r"(b[1]));
}

// convert 8 consecutive fp32 -> packed bf16 hi/lo (4 u32 each)
__device__ __forceinline__ void split_pack8(const float* g, uint32_t* ah, uint32_t* al) {
    float4 v0 = *(const float4*)g, v1 = *(const float4*)(g + 4);
    float f[8] = {v0.x, v0.y, v0.z, v0.w, v1.x, v1.y, v1.z, v1.w};
    #pragma unroll
    for (int i = 0; i < 4; i++) {
        __nv_bfloat16 h0 = __float2bfloat16(f[2*i]);
        __nv_bfloat16 h1 = __float2bfloat16(f[2*i+1]);
        __nv_bfloat162 hh; hh.x = h0; hh.y = h1;
        ah[i] = *(uint32_t*)&hh;
        __nv_bfloat162 ll;
        ll.x = __float2bfloat16(f[2*i]   - __bfloat162float(h0));
        ll.y = __float2bfloat16(f[2*i+1] - __bfloat162float(h1));
        al[i] = *(uint32_t*)&ll;
    }
}

// fragment compute over one 32-k chunk (smem tiles bf16 [64][40])
__device__ __forceinline__ void mma_chunk(
    const __nv_bfloat16* sAh, const __nv_bfloat16* sAl,
    const __nv_bfloat16* sBh, const __nv_bfloat16* sBl,
    int warp_m, int warp_n, int lane, float4 c[2][2])
{
    int grp = lane >> 2, tig = lane & 3;
    #pragma unroll
    for (int ks = 0; ks < 32; ks += 16) {
        uint32_t ah[2][4], al[2][4], bh[2][2], bl[2][2];
        #pragma unroll
        for (int i = 0; i < 2; i++) {
            int r = warp_m * 32 + i * 16 + grp;
            const __nv_bfloat16* ph = sAh + r * 40 + ks + tig * 2;
            const __nv_bfloat16* pl = sAl + r * 40 + ks + tig * 2;
            ah[i][0] = *(const uint32_t*)(ph);
            ah[i][1] = *(const uint32_t*)(ph + 8 * 40);
            ah[i][2] = *(const uint32_t*)(ph + 8);
            ah[i][3] = *(const uint32_t*)(ph + 8 * 40 + 8);
            al[i][0] = *(const uint32_t*)(pl);
            al[i][1] = *(const uint32_t*)(pl + 8 * 40);
            al[i][2] = *(const uint32_t*)(pl + 8);
            al[i][3] = *(const uint32_t*)(pl + 8 * 40 + 8);
        }
        #pragma unroll
        for (int j = 0; j < 2; j++) {
            int n = warp_n * 16 + j * 8 + grp;
            const __nv_bfloat16* ph = sBh + n * 40 + ks + tig * 2;
            const __nv_bfloat16* pl = sBl + n * 40 + ks + tig * 2;
            bh[j][0] = *(const uint32_t*)(ph);
            bh[j][1] = *(const uint32_t*)(ph + 8);
            bl[j][0] = *(const uint32_t*)(pl);
            bl[j][1] = *(const uint32_t*)(pl + 8);
        }
        #pragma unroll
        for (int i = 0; i < 2; i++)
            #pragma unroll
            for (int j = 0; j < 2; j++) {
                mma16816(c[i][j], ah[i], bh[j]);
                mma16816(c[i][j], ah[i], bl[j]);
                mma16816(c[i][j], al[i], bh[j]);
            }
    }
}

// ---------------- weight prep: fp32 -> bf16 hi/lo (with K padding) ----------------
__global__ void k_cvt(const float* __restrict__ src, __nv_bfloat16* __restrict__ hi,
                      __nv_bfloat16* __restrict__ lo, int C, int Cp, long total)
{
    long idx = (long)blockIdx.x * blockDim.x + threadIdx.x;
    if (idx >= total) return;
    long r = idx / Cp; int cc = (int)(idx % Cp);
    float v = (cc < C) ? src[r * C + cc] : 0.f;
    __nv_bfloat16 h = __float2bfloat16(v);
    hi[idx] = h;
    lo[idx] = __float2bfloat16(v - __bfloat162float(h));
}
__global__ void k_cvt_t(const float* __restrict__ src)  // wy [K][N] -> [n][k]
{
    int idx = blockIdx.x * blockDim.x + threadIdx.x;   // n*HH + k
    int n = idx >> 10, k = idx & 1023;
    float v = src[(size_t)k * HH + n];
    __nv_bfloat16 h = __float2bfloat16(v);
    c_wyt_hi[idx] = h;
    c_wyt_lo[idx] = __float2bfloat16(v - __bfloat162float(h));
}

// ---------------- init (state + LUT fused) ----------------
__global__ void k_initlut() {
    int i = blockIdx.x * blockDim.x + threadIdx.x;
    if (i < LUT_N) {
        float v  = tanhf(i * LUT_D);
        float vp = tanhf((i + 1) * LUT_D);
        float vm = tanhf((i - 1) * LUT_D);
        g_lut[i] = make_float2(v, (vp - vm) * 0.5f);
    }
    if (i < BB * HH) {
        g_c[i] = 0.f; g_cc[i] = 0.f; g_r[i] = 0.f;
        __nv_bfloat16 z = __float2bfloat16(0.f);
        g_hsA_hi[i] = z; g_hsA_lo[i] = z;
        g_hsB_hi[i] = z; g_hsB_lo[i] = z;
    }
}
__global__ void k_prep_hyp() {   // h0 = 0 (parity-0 split buffers), c0 = masked last premise cell
    int i = blockIdx.x * blockDim.x + threadIdx.x;
    if (i < BB * HH) {
        g_c[i] = g_cc[i];
        __nv_bfloat16 z = __float2bfloat16(0.f);
        g_hsA_hi[i] = z; g_hsA_lo[i] = z;
    }
}

// ---------------- mma embed: out = gather(emb)[M x K] @ wih^T + biases ----------------
__global__ void __launch_bounds__(256) k_mma_embed(
    const int* __restrict__ toks, int S,
    const __nv_bfloat16* __restrict__ Bhi, const __nv_bfloat16* __restrict__ Blo,
    const float* __restrict__ bih, const float* __restrict__ bhh, float* __restrict__ outp)
{
    __shared__ __nv_bfloat16 sAh[64*40], sAl[64*40], sBh[64*40], sBl[64*40];
    __shared__ int stok[64];
    int tid = threadIdx.x, lane = tid & 31, wid = tid >> 5;
    int warp_m = wid >> 2, warp_n = wid & 3;
    int m0 = blockIdx.y * 64, n0 = blockIdx.x * 64;
    if (tid < 64) { int m = m0 + tid; stok[tid] = toks[(m & (BB-1)) * S + (m >> 7)]; }
    __syncthreads();

    int srow = tid >> 2, skq = (tid & 3) * 8;
    const __nv_bfloat16* arow_hi;
    const __nv_bfloat16* arow_lo;
    {
        size_t base = (size_t)stok[srow] * EEP;
        arow_hi = c_emb_hi + base; arow_lo = c_emb_lo + base;
    }
    size_t bbase = (size_t)(n0 + srow) * EEP;

    float4 c[2][2] = {};
    uint4 pAh, pAl, pBh, pBl;
    pAh = *(const uint4*)(arow_hi + skq);
    pAl = *(const uint4*)(arow_lo + skq);
    pBh = *(const uint4*)(Bhi + bbase + skq);
    pBl = *(const uint4*)(Blo + bbase + skq);

    const int KC = EEP / 32;
    for (int ck = 0; ck < KC; ck++) {
        *(uint4*)&sAh[srow*40 + skq] = pAh;
        *(uint4*)&sAl[srow*40 + skq] = pAl;
        *(uint4*)&sBh[srow*40 + skq] = pBh;
        *(uint4*)&sBl[srow*40 + skq] = pBl;
        __syncthreads();
        if (ck + 1 < KC) {
            int k0 = (ck + 1) * 32;
            pAh = *(const uint4*)(arow_hi + k0 + skq);
            pAl = *(const uint4*)(arow_lo + k0 + skq);
            pBh = *(const uint4*)(Bhi + bbase + k0 + skq);
            pBl = *(const uint4*)(Blo + bbase + k0 + skq);
        }
        mma_chunk(sAh, sAl, sBh, sBl, warp_m, warp_n, lane, c);
        __syncthreads();
    }

    int grp = lane >> 2, tig = lane & 3;
    #pragma unroll
    for (int i = 0; i < 2; i++) {
        int r = m0 + warp_m * 32 + i * 16 + grp;
        #pragma unroll
        for (int j = 0; j < 2; j++) {
            int n = n0 + warp_n * 16 + j * 8 + tig * 2;
            float b0 = bih[n] + bhh[n], b1 = bih[n+1] + bhh[n+1];
            outp[(size_t)r * G4 + n]       = c[i][j].x + b0;
            outp[(size_t)r * G4 + n + 1]   = c[i][j].y + b1;
            outp[(size_t)(r+8) * G4 + n]   = c[i][j].z + b0;
            outp[(size_t)(r+8) * G4 + n+1] = c[i][j].w + b1;
        }
    }
}

// ---------------- mma first: g_first = g_outp @ wy ----------------
__global__ void __launch_bounds__(256) k_mma_first()
{
    __shared__ __nv_bfloat16 sAh[64*40], sAl[64*40], sBh[64*40], sBl[64*40];
    int tid = threadIdx.x, lane = tid & 31, wid = tid >> 5;
    int warp_m = wid >> 2, warp_n = wid & 3;
    int m0 = blockIdx.y * 64, n0 = blockIdx.x * 64;

    int srow = tid >> 2, skq = (tid & 3) * 8;
    const float* arow = g_outp + (size_t)(m0 + srow) * HH;
    size_t bbase = (size_t)(n0 + srow) * HH;

    float4 c[2][2] = {};
    uint32_t pAh[4], pAl[4]; uint4 pBh, pBl;
    split_pack8(arow + skq, pAh, pAl);
    pBh = *(const uint4*)(c_wyt_hi + bbase + skq);
    pBl = *(const uint4*)(c_wyt_lo + bbase + skq);

    const int KC = HH / 32;
    for (int ck = 0; ck < KC; ck++) {
        *(uint4*)&sAh[srow*40 + skq] = make_uint4(pAh[0], pAh[1], pAh[2], pAh[3]);
        *(uint4*)&sAl[srow*40 + skq] = make_uint4(pAl[0], pAl[1], pAl[2], pAl[3]);
        *(uint4*)&sBh[srow*40 + skq] = pBh;
        *(uint4*)&sBl[srow*40 + skq] = pBl;
        __syncthreads();
        if (ck + 1 < KC) {
            int k0 = (ck + 1) * 32;
            split_pack8(arow + k0 + skq, pAh, pAl);
            pBh = *(const uint4*)(c_wyt_hi + bbase + k0 + skq);
            pBl = *(const uint4*)(c_wyt_lo + bbase + k0 + skq);
        }
        mma_chunk(sAh, sAl, sBh, sBl, warp_m, warp_n, lane, c);
        __syncthreads();
    }

    int grp = lane >> 2, tig = lane & 3;
    #pragma unroll
    for (int i = 0; i < 2; i++) {
        int r = m0 + warp_m * 32 + i * 16 + grp;
        #pragma unroll
        for (int j = 0; j < 2; j++) {
            int n = n0 + warp_n * 16 + j * 8 + tig * 2;
            g_first[(size_t)r * HH + n]       = c[i][j].x;
            g_first[(size_t)r * HH + n + 1]   = c[i][j].y;
            g_first[(size_t)(r+8) * HH + n]   = c[i][j].z;
            g_first[(size_t)(r+8) * HH + n+1] = c[i][j].w;
        }
    }
}

// ---------------- mma LSTM step (fused pointwise, pre-split h, EXACT activations) ----------------
// Block: 64 batch x (16 h-cols x 4 gates). Grid: dim3(HH/16=64, 2).
// Double-buffered smem: ONE __syncthreads per k-chunk (32 barriers/step instead of 64).
__global__ void __launch_bounds__(256) k_mma_lstm(
    const __nv_bfloat16* __restrict__ Whi, const __nv_bfloat16* __restrict__ Wlo,
    const float* __restrict__ xw, const int* __restrict__ toks, int S, int t, int which)
{
    const __nv_bfloat16* hin_hi = (t & 1) ? g_hsB_hi : g_hsA_hi;
    const __nv_bfloat16* hin_lo = (t & 1) ? g_hsB_lo : g_hsA_lo;
    __nv_bfloat16* hout_hi = (t & 1) ? g_hsA_hi : g_hsB_hi;
    __nv_bfloat16* hout_lo = (t & 1) ? g_hsA_lo : g_hsB_lo;

    // 2 buffer sets x 4 tiles x (64 rows x 40 bf16) = 40960 B; Gs reuses set 0 after loop
    __shared__ __align__(16) char pool[2 * 4 * 64 * 40 * 2];
    float* Gs = (float*)pool;   // [64][68] = 17408 B (< 20480-byte buffer set)

    int tid = threadIdx.x, lane = tid & 31, wid = tid >> 5;
    int warp_m = wid >> 2, warp_n = wid & 3;
    int m0 = blockIdx.y * 64;        // batch offset
    int h0 = blockIdx.x * 16;        // h-col offset

    int srow = tid >> 2, skq = (tid & 3) * 8;
    const __nv_bfloat16* arow_hi = hin_hi + (size_t)(m0 + srow) * HH;
    const __nv_bfloat16* arow_lo = hin_lo + (size_t)(m0 + srow) * HH;
    int gate = srow >> 4, hh = srow & 15;
    size_t bbase = (size_t)(gate * HH + h0 + hh) * HH;

    float4 c[2][2] = {};
    uint4 pAh, pAl, pBh, pBl;
    pAh = *(const uint4*)(arow_hi + skq);
    pAl = *(const uint4*)(arow_lo + skq);
    pBh = *(const uint4*)(Whi + bbase + skq);
    pBl = *(const uint4*)(Wlo + bbase + skq);

    const int KC = HH / 32;
    for (int ck = 0; ck < KC; ck++) {
        char* buf = pool + (ck & 1) * 20480;
        __nv_bfloat16* sAh = (__nv_bfloat16*)(buf);
        __nv_bfloat16* sAl = (__nv_bfloat16*)(buf + 5120);
        __nv_bfloat16* sBh = (__nv_bfloat16*)(buf + 10240);
        __nv_bfloat16* sBl = (__nv_bfloat16*)(buf + 15360);
        *(uint4*)&sAh[srow*40 + skq] = pAh;
        *(uint4*)&sAl[srow*40 + skq] = pAl;
        *(uint4*)&sBh[srow*40 + skq] = pBh;
        *(uint4*)&sBl[srow*40 + skq] = pBl;
        __syncthreads();
        if (ck + 1 < KC) {
            int k0 = (ck + 1) * 32;
            pAh = *(const uint4*)(arow_hi + k0 + skq);
            pAl = *(const uint4*)(arow_lo + k0 + skq);
            pBh = *(const uint4*)(Whi + bbase + k0 + skq);
            pBl = *(const uint4*)(Wlo + bbase + k0 + skq);
        }
        mma_chunk(sAh, sAl, sBh, sBl, warp_m, warp_n, lane, c);
        // no trailing sync: next iteration writes the OTHER buffer; its sync
        // guarantees every warp has finished this chunk before buffer reuse.
    }
    __syncthreads();   // all compute done before Gs overlays buffer set 0

    // gate preactivations -> Gs[batch64][col = gate*16 + hh]
    {
        int grp = lane >> 2, tig = lane & 3;
        #pragma unroll
        for (int i = 0; i < 2; i++) {
            int r = warp_m * 32 + i * 16 + grp;
            #pragma unroll
            for (int j = 0; j < 2; j++) {
                int n = warp_n * 16 + j * 8 + tig * 2;
                Gs[r * 68 + n]         = c[i][j].x;
                Gs[r * 68 + n + 1]     = c[i][j].y;
                Gs[(r+8) * 68 + n]     = c[i][j].z;
                Gs[(r+8) * 68 + n + 1] = c[i][j].w;
            }
        }
    }
    __syncthreads();

    // pointwise: EXACT activations (recurrence must not take approximation error)
    {
        int q = tid * 4;
        int b64 = q >> 4, hh4 = q & 15;
        int b = m0 + b64;
        int h = h0 + hh4;
        float m = (toks[b * S + t] != 0) ? 1.f : 0.f;
        float im = 1.f - m;
        const float* xr = xw + ((size_t)t * BB + b) * G4 + h;
        float4 gi = *(float4*)&Gs[b64 * 68 +  0 + hh4];
        float4 gf = *(float4*)&Gs[b64 * 68 + 16 + hh4];
        float4 gg = *(float4*)&Gs[b64 * 68 + 32 + hh4];
        float4 go = *(float4*)&Gs[b64 * 68 + 48 + hh4];
        float4 xi = *(const float4*)&xr[0 * HH];
        float4 xf = *(const float4*)&xr[1 * HH];
        float4 xg = *(const float4*)&xr[2 * HH];
        float4 xo = *(const float4*)&xr[3 * HH];
        float4 cc = *(float4*)&g_c[b * HH + h];
        float giv[4] = {gi.x + xi.x, gi.y + xi.y, gi.z + xi.z, gi.w + xi.w};
        float gfv[4] = {gf.x + xf.x, gf.y + xf.y, gf.z + xf.z, gf.w + xf.w};
        float ggv[4] = {gg.x + xg.x, gg.y + xg.y, gg.z + xg.z, gg.w + xg.w};
        float gov[4] = {go.x + xo.x, go.y + xo.y, go.z + xo.z, go.w + xo.w};
        float cv[4] = {cc.x, cc.y, cc.z, cc.w};
        float c2v[4], h2v[4];
        #pragma unroll
        for (int i = 0; i < 4; i++) {
            float iv = sigm(giv[i]), fv = sigm(gfv[i]);
            float gv = tanhf(ggv[i]), ov = sigm(gov[i]);
            float c2 = fv * cv[i] + iv * gv;
            c2v[i] = c2;
            h2v[i] = ov * tanhf(c2);
        }
        float4 c2f = make_float4(c2v[0], c2v[1], c2v[2], c2v[3]);
        float4 h2f = make_float4(h2v[0], h2v[1], h2v[2], h2v[3]);
        *(float4*)&g_c[b * HH + h] = c2f;

        // write raw h as bf16 hi/lo split (next step's A operand)
        {
            __nv_bfloat162 hi01, hi23, lo01, lo23;
            hi01.x = __float2bfloat16(h2v[0]); hi01.y = __float2bfloat16(h2v[1]);
            hi23.x = __float2bfloat16(h2v[2]); hi23.y = __float2bfloat16(h2v[3]);
            lo01.x = __float2bfloat16(h2v[0] - __bfloat162float(hi01.x));
            lo01.y = __float2bfloat16(h2v[1] - __bfloat162float(hi01.y));
            lo23.x = __float2bfloat16(h2v[2] - __bfloat162float(hi23.x));
            lo23.y = __float2bfloat16(h2v[3] - __bfloat162float(hi23.y));
            uint2 phi = make_uint2(*(uint32_t*)&hi01, *(uint32_t*)&hi23);
            uint2 plo = make_uint2(*(uint32_t*)&lo01, *(uint32_t*)&lo23);
            *(uint2*)&hout_hi[b * HH + h] = phi;
            *(uint2*)&hout_lo[b * HH + h] = plo;
        }

        if (which == 0) {
            float4 prev = make_float4(0.f, 0.f, 0.f, 0.f);
            if (t > 0) prev = *(float4*)&g_outp[((size_t)b * SPP + (t - 1)) * HH + h];
            *(float4*)&g_outp[((size_t)b * SPP + t) * HH + h] = make_float4(
                m * h2f.x + im * prev.x, m * h2f.y + im * prev.y,
                m * h2f.z + im * prev.z, m * h2f.w + im * prev.w);
            float4 pc = *(float4*)&g_cc[b * HH + h];
            *(float4*)&g_cc[b * HH + h] = make_float4(
                m * c2f.x + im * pc.x, m * c2f.y + im * pc.y,
                m * c2f.z + im * pc.z, m * c2f.w + im * pc.w);
        } else {
            float4 prev = make_float4(0.f, 0.f, 0.f, 0.f);
            if (t > 0) prev = *(float4*)&g_outh[((size_t)(t - 1) * BB + b) * HH + h];
            *(float4*)&g_outh[((size_t)t * BB + b) * HH + h] = make_float4(
                m * h2f.x + im * prev.x, m * h2f.y + im * prev.y,
                m * h2f.z + im * prev.z, m * h2f.w + im * prev.w);
        }
    }
}

// ---------------- fused second + trt (fp32 SIMT, 128-block tiling) ----------------
// BN=16, micro 2x2, grid (HH/16=64, 2): all SMs engaged; per-element accumulation
// order unchanged (k-sequential) -> bitwise identical results to the 64-block version.
__global__ void __launch_bounds__(256) k_secondtrt(
    const float* __restrict__ wh_, const float* __restrict__ wr_,
    const float* __restrict__ wt_, int t)
{
    __shared__ float As1[32][68];   // outh_t
    __shared__ float As2[32][68];   // r
    __shared__ float Bs1[32][20];
    __shared__ float Bs2[32][20];
    __shared__ float Bs3[32][20];
    const float* A1 = g_outh + (size_t)t * BB * HH;
    const int K = HH, N = HH;
    int tid = threadIdx.x;
    int n0 = blockIdx.x * 16, m0 = blockIdx.y * 64;
    int ty = tid >> 3, tx = tid & 7;          // ty 0..31 (2 rows each), tx 0..7 (2 cols each)
    int alm = tid / 4, alk = (tid % 4) * 8;
    int bk = tid >> 3, bn = (tid & 7) * 2;    // B loads: 32 k-rows x 16 n, float2/thread
    float acc1[2][2] = {};
    float acc2[2][2] = {};

    for (int k0 = 0; k0 < K; k0 += 32) {
        {
            const float4* ap = (const float4*)&A1[(size_t)(m0 + alm) * K + k0 + alk];
            float4 v0 = ap[0], v1 = ap[1];
            As1[alk + 0][alm] = v0.x; As1[alk + 1][alm] = v0.y; As1[alk + 2][alm] = v0.z; As1[alk + 3][alm] = v0.w;
            As1[alk + 4][alm] = v1.x; As1[alk + 5][alm] = v1.y; As1[alk + 6][alm] = v1.z; As1[alk + 7][alm] = v1.w;
        }
        {
            const float4* ap = (const float4*)&g_r[(size_t)(m0 + alm) * K + k0 + alk];
            float4 v0 = ap[0], v1 = ap[1];
            As2[alk + 0][alm] = v0.x; As2[alk + 1][alm] = v0.y; As2[alk + 2][alm] = v0.z; As2[alk + 3][alm] = v0.w;
            As2[alk + 4][alm] = v1.x; As2[alk + 5][alm] = v1.y; As2[alk + 6][alm] = v1.z; As2[alk + 7][alm] = v1.w;
        }
        {
            *(float2*)&Bs1[bk][bn] = *(const float2*)&wh_[(size_t)(k0 + bk) * N + n0 + bn];
            *(float2*)&Bs2[bk][bn] = *(const float2*)&wr_[(size_t)(k0 + bk) * N + n0 + bn];
            *(float2*)&Bs3[bk][bn] = *(const float2*)&wt_[(size_t)(k0 + bk) * N + n0 + bn];
        }
        __syncthreads();
        #pragma unroll
        for (int k = 0; k < 32; k++) {
            float a0 = As1[k][ty * 2 + 0], a1 = As1[k][ty * 2 + 1];
            float c0 = As2[k][ty * 2 + 0], c1 = As2[k][ty * 2 + 1];
            float2 b1 = *(const float2*)&Bs1[k][tx * 2];
            float2 b2 = *(const float2*)&Bs2[k][tx * 2];
            float2 b3 = *(const float2*)&Bs3[k][tx * 2];
            acc1[0][0] += a0 * b1.x + c0 * b2.x; acc1[0][1] += a0 * b1.y + c0 * b2.y;
            acc1[1][0] += a1 * b1.x + c1 * b2.x; acc1[1][1] += a1 * b1.y + c1 * b2.y;
            acc2[0][0] += c0 * b3.x; acc2[0][1] += c0 * b3.y;
            acc2[1][0] += c1 * b3.x; acc2[1][1] += c1 * b3.y;
        }
        __syncthreads();
    }
    #pragma unroll
    for (int i = 0; i < 2; i++) {
        int m = m0 + ty * 2 + i;
        #pragma unroll
        for (int j = 0; j < 2; j++) {
            int n = n0 + tx * 2 + j;
            g_second[(size_t)m * HH + n] = acc1[i][j];
            g_trt[(size_t)m * HH + n]    = acc2[i][j];
        }
    }
}

// ---------------- fused scan step: score (LUT) + softmax + r update, one block per b ----------------
__global__ void __launch_bounds__(512) k_scanstep(const int* __restrict__ prem,
                                                  const int* __restrict__ hyp,
                                                  const float* __restrict__ w_, int t)
{
    __shared__ float2 slut[LUT_N];
    __shared__ float ssec[HH];
    __shared__ float sw[HH];
    __shared__ float sc[SPP];
    __shared__ float al[SPP];
    int b = blockIdx.x, tid = threadIdx.x;
    int lane = tid & 31, wid = tid >> 5;

    slut[tid]       = g_lut[tid];
    slut[tid + 512] = g_lut[tid + 512];
    ssec[tid]       = g_second[b * HH + tid];
    ssec[tid + 512] = g_second[b * HH + tid + 512];
    sw[tid]         = w_[tid];
    sw[tid + 512]   = w_[tid + 512];
    __syncthreads();

    // scores: warp w handles p = w*8 .. w*8+7 (LUT tanh: one-shot path, proven safe)
    #pragma unroll 1
    for (int i = 0; i < 8; i++) {
        int p = wid * 8 + i;
        const float4* frow = (const float4*)(g_first + ((size_t)b * SPP + p) * HH);
        float acc = 0.f;
        #pragma unroll
        for (int j = 0; j < 8; j++) {
            int idx = j * 32 + lane;
            float4 f  = frow[idx];
            float4 s  = *(const float4*)&ssec[idx * 4];
            float4 ww = *(const float4*)&sw[idx * 4];
            acc += tanh_lut(f.x + s.x, slut) * ww.x + tanh_lut(f.y + s.y, slut) * ww.y
                 + tanh_lut(f.z + s.z, slut) * ww.z + tanh_lut(f.w + s.w, slut) * ww.w;
        }
        #pragma unroll
        for (int o = 16; o > 0; o >>= 1) acc += __shfl_down_sync(0xffffffffu, acc, o);
        if (lane == 0)
            sc[p] = acc + ((prem[b * SPP + p] != 0) ? 0.f : -1000.f);
    }
    __syncthreads();

    // softmax by warp 0
    if (wid == 0) {
        float v0 = sc[lane], v1 = sc[lane+32], v2 = sc[lane+64], v3 = sc[lane+96];
        float mx = fmaxf(fmaxf(v0, v1), fmaxf(v2, v3));
        #pragma unroll
        for (int o = 16; o > 0; o >>= 1) mx = fmaxf(mx, __shfl_xor_sync(0xffffffffu, mx, o));
        float e0 = expf(v0-mx), e1 = expf(v1-mx), e2 = expf(v2-mx), e3 = expf(v3-mx);
        float ss = e0 + e1 + e2 + e3;
        #pragma unroll
        for (int o = 16; o > 0; o >>= 1) ss += __shfl_xor_sync(0xffffffffu, ss, o);
        float inv = 1.f / ss;
        al[lane]    = e0 * inv; al[lane+32] = e1 * inv;
        al[lane+64] = e2 * inv; al[lane+96] = e3 * inv;
    }
    __syncthreads();

    // r update: EXACT tanhf (feeds the 64-step r recurrence; LUT here failed R10/R12)
    {
        int h = tid * 2;
        const float* yb = g_outp + (size_t)b * SPP * HH + h;
        float ax = 0.f, ay = 0.f;
        #pragma unroll 4
        for (int p = 0; p < SPP; p++) {
            float a = al[p];
            float2 y = *(const float2*)&yb[(size_t)p * HH];
            ax += a * y.x; ay += a * y.y;
        }
        float2 tr = *(const float2*)&g_trt[b * HH + h];
        float rt0 = ax + tanhf(tr.x);
        float rt1 = ay + tanhf(tr.y);
        float m = (hyp[b * SHH + t] != 0) ? 1.f : 0.f;
        float im = 1.f - m;
        float2 r = *(float2*)&g_r[b * HH + h];
        *(float2*)&g_r[b * HH + h] = make_float2(m * rt0 + im * r.x, m * rt1 + im * r.y);
    }
}

// ---------------- small-M fp32 GEMM (h_star) ----------------
__global__ void __launch_bounds__(256) k_hstar(const float* __restrict__ wp_, const float* __restrict__ wx_)
{
    __shared__ float As1[32][68];
    __shared__ float As2[32][68];
    __shared__ float Bs1[32][36];
    __shared__ float Bs2[32][36];
    const float* A1 = g_r;
    const float* A2 = g_outh + (size_t)(SHH - 1) * BB * HH;
    const int K = HH, N = HH;
    int tid = threadIdx.x;
    int n0 = blockIdx.x * 32, m0 = blockIdx.y * 64;
    int ty = tid / 8, tx = tid % 8;
    int alm = tid / 4, alk = (tid % 4) * 8;
    float acc[2][4] = {};

    for (int k0 = 0; k0 < K; k0 += 32) {
        {
            const float4* ap = (const float4*)&A1[(size_t)(m0 + alm) * K + k0 + alk];
            float4 v0 = ap[0], v1 = ap[1];
            As1[alk + 0][alm] = v0.x; As1[alk + 1][alm] = v0.y; As1[alk + 2][alm] = v0.z; As1[alk + 3][alm] = v0.w;
            As1[alk + 4][alm] = v1.x; As1[alk + 5][alm] = v1.y; As1[alk + 6][alm] = v1.z; As1[alk + 7][alm] = v1.w;
        }
        {
            const float4* ap = (const float4*)&A2[(size_t)(m0 + alm) * K + k0 + alk];
            float4 v0 = ap[0], v1 = ap[1];
            As2[alk + 0][alm] = v0.x; As2[alk + 1][alm] = v0.y; As2[alk + 2][alm] = v0.z; As2[alk + 3][alm] = v0.w;
            As2[alk + 4][alm] = v1.x; As2[alk + 5][alm] = v1.y; As2[alk + 6][alm] = v1.z; As2[alk + 7][alm] = v1.w;
        }
        {
            int bk = tid / 8, bn = (tid % 8) * 4;
            *(float4*)&Bs1[bk][bn] = *(const float4*)&wp_[(size_t)(k0 + bk) * N + n0 + bn];
            *(float4*)&Bs2[bk][bn] = *(const float4*)&wx_[(size_t)(k0 + bk) * N + n0 + bn];
        }
        __syncthreads();
        #pragma unroll
        for (int k = 0; k < 32; k++) {
            float a0 = As1[k][ty * 2 + 0], a1 = As1[k][ty * 2 + 1];
            float c0 = As2[k][ty * 2 + 0], c1 = As2[k][ty * 2 + 1];
            float4 b = *(const float4*)&Bs1[k][tx * 4];
            float4 d = *(const float4*)&Bs2[k][tx * 4];
            acc[0][0] += a0 * b.x + c0 * d.x; acc[0][1] += a0 * b.y + c0 * d.y;
            acc[0][2] += a0 * b.z + c0 * d.z; acc[0][3] += a0 * b.w + c0 * d.w;
            acc[1][0] += a1 * b.x + c1 * d.x; acc[1][1] += a1 * b.y + c1 * d.y;
            acc[1][2] += a1 * b.z + c1 * d.z; acc[1][3] += a1 * b.w + c1 * d.w;
        }
        __syncthreads();
    }
    #pragma unroll
    for (int i = 0; i < 2; i++) {
        int m = m0 + ty * 2 + i;
        #pragma unroll
        for (int j = 0; j < 4; j++)
            g_hstar[(size_t)m * N + n0 + tx * 4 + j] = acc[i][j];
    }
}

// ---------------- logits + final softmax ----------------
__global__ void __launch_bounds__(256) k_logits(const float* __restrict__ fcw,
                                                const float* __restrict__ fcb,
                                                float* __restrict__ out)
{
    int b = blockIdx.x, tid = threadIdx.x;
    float a0 = 0.f, a1 = 0.f, a2 = 0.f, a3 = 0.f;
    for (int h = tid; h < HH; h += 256) {
        float hs = tanhf(g_hstar[b * HH + h]);
        a0 += hs * fcw[0 * HH + h];
        a1 += hs * fcw[1 * HH + h];
        a2 += hs * fcw[2 * HH + h];
        a3 += hs * fcw[3 * HH + h];
    }
    __shared__ float sm[4][256];
    sm[0][tid] = a0; sm[1][tid] = a1; sm[2][tid] = a2; sm[3][tid] = a3;
    __syncthreads();
    for (int s = 128; s > 0; s >>= 1) {
        if (tid < s) {
            #pragma unroll
            for (int c = 0; c < 4; c++) sm[c][tid] += sm[c][tid + s];
        }
        __syncthreads();
    }
    if (tid == 0) {
        float l[4]; float mx = -1e30f;
        #pragma unroll
        for (int c = 0; c < 4; c++) { l[c] = sm[c][0] + fcb[c]; mx = fmaxf(mx, l[c]); }
        float s = 0.f;
        #pragma unroll
        for (int c = 0; c < 4; c++) { l[c] = expf(l[c] - mx); s += l[c]; }
        #pragma unroll
        for (int c = 0; c < 4; c++) out[b * 4 + c] = l[c] / s;
    }
}

// ---------------- launch ----------------
extern "C" void kernel_launch(void* const* d_in, const int* in_sizes, int n_in,
                              void* d_out, int out_size)
{
    (void)in_sizes; (void)n_in; (void)out_size;
    const int*   prem   = (const int*)d_in[0];
    const int*   hyp    = (const int*)d_in[1];
    const float* emb    = (const float*)d_in[2];
    const float* w_ih_p = (const float*)d_in[3];
    const float* w_hh_p = (const float*)d_in[4];
    const float* b_ih_p = (const float*)d_in[5];
    const float* b_hh_p = (const float*)d_in[6];
    const float* w_ih_h = (const float*)d_in[7];
    const float* w_hh_h = (const float*)d_in[8];
    const float* b_ih_h = (const float*)d_in[9];
    const float* b_hh_h = (const float*)d_in[10];
    const float* wy     = (const float*)d_in[11];
    const float* wh     = (const float*)d_in[12];
    const float* wr     = (const float*)d_in[13];
    const float* w      = (const float*)d_in[14];
    const float* wt     = (const float*)d_in[15];
    const float* wp     = (const float*)d_in[16];
    const float* wx     = (const float*)d_in[17];
    const float* fc_w   = (const float*)d_in[18];
    const float* fc_b   = (const float*)d_in[19];
    float* out = (float*)d_out;

    float* xwp; cudaGetSymbolAddress((void**)&xwp, g_xwp);
    float* xwh; cudaGetSymbolAddress((void**)&xwh, g_xwh);
    __nv_bfloat16 *embH, *embL, *wihpH, *wihpL, *wihhH, *wihhL, *whhpH, *whhpL, *whhhH, *whhhL;
    cudaGetSymbolAddress((void**)&embH,  c_emb_hi);  cudaGetSymbolAddress((void**)&embL,  c_emb_lo);
    cudaGetSymbolAddress((void**)&wihpH, c_wihp_hi); cudaGetSymbolAddress((void**)&wihpL, c_wihp_lo);
    cudaGetSymbolAddress((void**)&wihhH, c_wihh_hi); cudaGetSymbolAddress((void**)&wihhL, c_wihh_lo);
    cudaGetSymbolAddress((void**)&whhpH, c_whhp_hi); cudaGetSymbolAddress((void**)&whhpL, c_whhp_lo);
    cudaGetSymbolAddress((void**)&whhhH, c_whhh_hi); cudaGetSymbolAddress((void**)&whhhL, c_whhh_lo);

    long n1 = (long)VV * EEP;
    long n2 = (long)G4 * EEP;
    long n3 = (long)G4 * HH;
    k_cvt<<<(unsigned)((n1 + 255) / 256), 256>>>(emb, embH, embL, EE, EEP, n1);
    k_cvt<<<(unsigned)((n2 + 255) / 256), 256>>>(w_ih_p, wihpH, wihpL, EE, EEP, n2);
    k_cvt<<<(unsigned)((n3 + 255) / 256), 256>>>(w_hh_p, whhpH, whhpL, HH, HH, n3);
    k_initlut<<<512, 256>>>();
    k_mma_embed<<<dim3(G4 / 64, (SPP * BB) / 64), 256>>>(prem, SPP, wihpH, wihpL, b_ih_p, b_hh_p, xwp);

    // premise LSTM
    for (int t = 0; t < SPP; t++)
        k_mma_lstm<<<dim3(HH / 16, 2), 256>>>(whhpH, whhpL, xwp, prem, SPP, t, 0);

    // deferred hyp-side prep (independent of premise LSTM)
    k_cvt<<<(unsigned)((n2 + 255) / 256), 256>>>(w_ih_h, wihhH, wihhL, EE, EEP, n2);
    k_cvt<<<(unsigned)((n3 + 255) / 256), 256>>>(w_hh_h, whhhH, whhhL, HH, HH, n3);
    k_cvt_t<<<(HH * HH) / 256, 256>>>(wy);
    k_mma_embed<<<dim3(G4 / 64, (SHH * BB) / 64), 256>>>(hyp, SHH, wihhH, wihhL, b_ih_h, b_hh_h, xwh);
    k_prep_hyp<<<512, 256>>>();

    // hypothesis LSTM
    for (int t = 0; t < SHH; t++)
        k_mma_lstm<<<dim3(HH / 16, 2), 256>>>(whhhH, whhhL, xwh, hyp, SHH, t, 1);

    // first = Y @ wy
    k_mma_first<<<dim3(HH / 64, (SPP * BB) / 64), 256>>>();

    // word-by-word attention scan
    for (int t = 0; t < SHH; t++) {
        k_secondtrt<<<dim3(HH / 16, 2), 256>>>(wh, wr, wt, t);
        k_scanstep<<<BB, 512>>>(prem, hyp, w, t);
    }

    k_hstar<<<dim3(32, 2), 256>>>(wp, wx);
    k_logits<<<BB, 256>>>(fc_w, fc_b, out);
}